// round 12
// baseline (speedup 1.0000x reference)
#include <cuda_runtime.h>
#include <cuda_fp16.h>
#include <math.h>
#include <stdint.h>

#define BATCH 2
#define SEQ   2048
#define EMB   512
#define HEADS 8
#define HDIM  64
#define MROWS 4096
#define KA    1024   // split activations: 8 blocks of [hi64|lo64] (fp16)
#define KW    512    // weights: single-term fp16

// ---------------------------------------------------------------------------
// Scratch (device globals; allocation in kernel_launch is forbidden)
// ---------------------------------------------------------------------------
__device__ __align__(16) __half g_bA1[MROWS * KA];    // query split
__device__ __align__(16) __half g_bA2[MROWS * KA];    // k input split
__device__ __align__(16) __half g_bA3[MROWS * KA];    // v input split
__device__ __align__(16) __half g_bW [5 * EMB * KW];  // weights (hi only)
__device__ __align__(16) __half g_Qb [MROWS * KA];    // per-head [hi64|lo64]
__device__ __align__(16) __half g_Kb [MROWS * KW];    // per-head hi64
__device__ __align__(16) __half g_Vb [MROWS * KW];    // per-head hi64
__device__ __align__(16) float  g_G  [MROWS * EMB];   // silu gate fp32
__device__ __align__(16) __half g_bX2[MROWS * KA];    // retention out split
__device__ __align__(16) float g_sin[SEQ * 32];
__device__ __align__(16) float g_cos[SEQ * 32];

// ---------------------------------------------------------------------------
// Helpers
// ---------------------------------------------------------------------------
__device__ __forceinline__ uint32_t smem_u32(const void* p) {
    uint32_t a;
    asm("{ .reg .u64 t; cvta.to.shared.u64 t, %1; cvt.u32.u64 %0, t; }"
        : "=r"(a) : "l"(p));
    return a;
}

__device__ __forceinline__ void mma_f16(float* c, uint32_t a0, uint32_t a1,
                                        uint32_t a2, uint32_t a3,
                                        uint32_t b0, uint32_t b1) {
    asm volatile(
        "mma.sync.aligned.m16n8k16.row.col.f32.f16.f16.f32 "
        "{%0,%1,%2,%3}, {%4,%5,%6,%7}, {%8,%9}, {%0,%1,%2,%3};\n"
        : "+f"(c[0]), "+f"(c[1]), "+f"(c[2]), "+f"(c[3])
        : "r"(a0), "r"(a1), "r"(a2), "r"(a3), "r"(b0), "r"(b1));
}

__device__ __forceinline__ void ldsm4(uint32_t* r, uint32_t addr) {
    asm volatile("ldmatrix.sync.aligned.m8n8.x4.shared.b16 {%0,%1,%2,%3}, [%4];"
                 : "=r"(r[0]), "=r"(r[1]), "=r"(r[2]), "=r"(r[3]) : "r"(addr));
}
__device__ __forceinline__ void ldsm4t(uint32_t* r, uint32_t addr) {
    asm volatile("ldmatrix.sync.aligned.m8n8.x4.trans.shared.b16 {%0,%1,%2,%3}, [%4];"
                 : "=r"(r[0]), "=r"(r[1]), "=r"(r[2]), "=r"(r[3]) : "r"(addr));
}

#define CP16(dst, src) \
    asm volatile("cp.async.cg.shared.global [%0], [%1], 16;" \
                 :: "r"((uint32_t)(dst)), "l"(src))
#define CP_COMMIT() asm volatile("cp.async.commit_group;" ::: "memory")
#define CP_WAIT0()  asm volatile("cp.async.wait_group 0;" ::: "memory")

__device__ __forceinline__ void hilo16(float x, __half& h, __half& l) {
    h = __float2half_rn(x);
    l = __float2half_rn(x - __half2float(h));
}
__device__ __forceinline__ uint32_t pk2h(__half a, __half b) {
    uint16_t lo = *(uint16_t*)&a, hi = *(uint16_t*)&b;
    return (uint32_t)lo | ((uint32_t)hi << 16);
}

// ---------------------------------------------------------------------------
// Rotary tables
// ---------------------------------------------------------------------------
__global__ void rope_k(float* __restrict__ st, float* __restrict__ ct) {
    int i = blockIdx.x * blockDim.x + threadIdx.x;
    if (i >= SEQ * 32) return;
    int n = i >> 5, p = i & 31;
    float theta = powf(10000.f, -(float)p * (1.0f / 31.0f));
    float sv, cv;
    sincosf((float)n * theta, &sv, &cv);
    st[i] = sv;
    ct[i] = cv;
}

// ---------------------------------------------------------------------------
// fp32 -> fp16 splits. Activations: [hi64|lo64] blocks; weights: hi only.
// ---------------------------------------------------------------------------
__device__ __forceinline__ void splitA4(const float* __restrict__ src,
                                        __half* __restrict__ dst, int idx) {
    int row = idx >> 7, c = (idx & 127) << 2;
    float4 v = *(const float4*)(src + (size_t)row * EMB + c);
    float x[4] = {v.x, v.y, v.z, v.w};
    __half h[4], l[4];
#pragma unroll
    for (int i = 0; i < 4; i++) hilo16(x[i], h[i], l[i]);
    uint2 hp, lp;
    hp.x = pk2h(h[0], h[1]); hp.y = pk2h(h[2], h[3]);
    lp.x = pk2h(l[0], l[1]); lp.y = pk2h(l[2], l[3]);
    size_t base = (size_t)row * KA + (c >> 6) * 128 + (c & 63);
    *(uint2*)(dst + base)      = hp;
    *(uint2*)(dst + base + 64) = lp;
}
__device__ __forceinline__ void splitW4(const float* __restrict__ src,
                                        __half* __restrict__ dst, int idx) {
    int row = idx >> 7, c = (idx & 127) << 2;
    float4 v = *(const float4*)(src + (size_t)row * EMB + c);
    __half h[4];
    h[0] = __float2half_rn(v.x); h[1] = __float2half_rn(v.y);
    h[2] = __float2half_rn(v.z); h[3] = __float2half_rn(v.w);
    uint2 hp;
    hp.x = pk2h(h[0], h[1]); hp.y = pk2h(h[2], h[3]);
    *(uint2*)(dst + (size_t)row * KW + c) = hp;
}

__global__ void convA_k(const float* __restrict__ s0, const float* __restrict__ s1,
                        const float* __restrict__ s2,
                        __half* __restrict__ d0, __half* __restrict__ d1,
                        __half* __restrict__ d2) {
    int idx = blockIdx.x * blockDim.x + threadIdx.x;
    if (idx >= MROWS * 128) return;
    const float* src; __half* dst;
    if (blockIdx.y == 0)      { src = s0; dst = d0; }
    else if (blockIdx.y == 1) { src = s1; dst = d1; }
    else                      { src = s2; dst = d2; }
    splitA4(src, dst, idx);
}

__global__ void convW_k(const float* __restrict__ s0, const float* __restrict__ s1,
                        const float* __restrict__ s2, const float* __restrict__ s3,
                        const float* __restrict__ s4, __half* __restrict__ dst) {
    int idx = blockIdx.x * blockDim.x + threadIdx.x;
    if (idx >= EMB * 128) return;
    const float* src;
    switch (blockIdx.y) {
        case 0: src = s0; break;
        case 1: src = s1; break;
        case 2: src = s2; break;
        case 3: src = s3; break;
        default: src = s4; break;
    }
    splitW4(src, dst + (size_t)blockIdx.y * EMB * KW, idx);
}

// ---------------------------------------------------------------------------
// Projection GEMM (merged): CTA tile 128m x 64n, warp tile 32x32 (4m x 2n
// warps). acc = 32 regs -> ~40 regs scheduling headroom under the 128 cap.
// 2-term fp16 A x single-term W, 8 chunks, single barrier per chunk.
// phase 0: z=0 Q(rotary,split), z=1 K(rotary*.125,hi), z=2 V(hi), z=3 G(silu)
// phase 1: output projection (fp32 out)
// ---------------------------------------------------------------------------
#define PJ_PA 272
#define PJ_PW 144
#define PJ_ABUF 34816              // 128 * 272
#define PJ_WBUF 9216               // 64 * 144
#define PJ_A0 0
#define PJ_W0 (2 * PJ_ABUF)        // 69632
#define PJ_SMEM (2 * PJ_ABUF + 2 * PJ_WBUF)   // 88064
#define PJ_CHUNKS 8

__global__ void __launch_bounds__(256, 2)
proj_all(const __half* __restrict__ bA1, const __half* __restrict__ bA2,
         const __half* __restrict__ bA3, const __half* __restrict__ bX2,
         const __half* __restrict__ bW,
         const float* __restrict__ bq, const float* __restrict__ bk,
         const float* __restrict__ bv, const float* __restrict__ bg,
         const float* __restrict__ bo,
         __half* __restrict__ Qb, __half* __restrict__ Kb,
         __half* __restrict__ Vb, float* __restrict__ Gf,
         float* __restrict__ outp, int phase)
{
    extern __shared__ char sm[];
    const uint32_t smb = smem_u32(sm);
    const int tid = threadIdx.x;
    const int lane = tid & 31, wid = tid >> 5;
    const int g = lane >> 2, tig = lane & 3;
    const int wm = wid >> 1, wn = wid & 1;
    const int mBase = blockIdx.y * 128, nBase = blockIdx.x * 64;
    const int z = blockIdx.z;

    const __half* A;
    const float* bias;
    int mode;
    void* Cout;
    const size_t wOff = (size_t)EMB * KW;
    const __half* W;
    if (phase == 0) {
        if (z == 0)      { A = bA1; W = bW;            bias = bq; mode = 2; Cout = Qb; }
        else if (z == 1) { A = bA2; W = bW + 1 * wOff; bias = bk; mode = 3; Cout = Kb; }
        else if (z == 2) { A = bA3; W = bW + 2 * wOff; bias = bv; mode = 4; Cout = Vb; }
        else             { A = bA1; W = bW + 3 * wOff; bias = bg; mode = 1; Cout = Gf; }
    } else {
        A = bX2; W = bW + 4 * wOff; bias = bo; mode = 0; Cout = outp;
    }

    const int aRow   = lane & 15;
    const int aOff16 = (lane >> 4) * 16;
    const int bRow   = (lane & 7) + ((lane >> 4) << 3);
    const int bOff16 = ((lane >> 3) & 1) * 16;

    float acc[2][4][4];
#pragma unroll
    for (int a = 0; a < 2; a++)
#pragma unroll
        for (int b = 0; b < 4; b++)
#pragma unroll
            for (int c = 0; c < 4; c++) acc[a][b][c] = 0.f;

    // A loads: 128 rows x 256 B per chunk; thread -> (row = tid>>1, half = tid&1)
    const int acrow = tid >> 1;
    const int acsel = tid & 1;
    const __half* Arow = A + (size_t)(mBase + acrow) * KA;
    // W loads: 64 rows x 128 B per chunk; thread -> (row = tid>>2, qtr = tid&3)
    const int wcrow = tid >> 2;
    const int wcsel = tid & 3;
    const __half* Wrow = W + (size_t)(nBase + wcrow) * KW;

#define LOADC(c) do {                                                          \
    const int _b = (c) & 1;                                                    \
    const uint32_t _ad = smb + PJ_A0 + _b * PJ_ABUF + acrow * PJ_PA + acsel * 128; \
    const __half* _as = Arow + (c) * 128 + acsel * 64;                         \
    _Pragma("unroll")                                                          \
    for (int _i = 0; _i < 8; _i++) CP16(_ad + _i * 16, _as + _i * 8);          \
    const uint32_t _wd = smb + PJ_W0 + _b * PJ_WBUF + wcrow * PJ_PW + wcsel * 32; \
    const __half* _ws = Wrow + (c) * 64 + wcsel * 16;                          \
    CP16(_wd, _ws);                                                            \
    CP16(_wd + 16, _ws + 8);                                                   \
} while (0)

    LOADC(0);
    CP_COMMIT();

    for (int c = 0; c < PJ_CHUNKS; c++) {
        CP_WAIT0();
        __syncthreads();
        if (c + 1 < PJ_CHUNKS) {
            LOADC(c + 1);
            CP_COMMIT();
        }
        const uint32_t aS = smb + PJ_A0 + (c & 1) * PJ_ABUF;
        const uint32_t wS = smb + PJ_W0 + (c & 1) * PJ_WBUF;
#pragma unroll
        for (int ks = 0; ks < 4; ks++) {
            uint32_t ah[2][4], al[2][4];
#pragma unroll
            for (int mt = 0; mt < 2; mt++) {
                const uint32_t ar = aS + (wm * 32 + mt * 16 + aRow) * PJ_PA;
                ldsm4(ah[mt], ar + ks * 32 + aOff16);
                ldsm4(al[mt], ar + 128 + ks * 32 + aOff16);
            }
#pragma unroll
            for (int nt2 = 0; nt2 < 2; nt2++) {
                uint32_t bvv[4];
                ldsm4(bvv, wS + (wn * 32 + nt2 * 16 + bRow) * PJ_PW
                           + ks * 32 + bOff16);
#pragma unroll
                for (int mt = 0; mt < 2; mt++) {
                    mma_f16(acc[mt][nt2 * 2 + 0],
                            ah[mt][0], ah[mt][1], ah[mt][2], ah[mt][3], bvv[0], bvv[1]);
                    mma_f16(acc[mt][nt2 * 2 + 0],
                            al[mt][0], al[mt][1], al[mt][2], al[mt][3], bvv[0], bvv[1]);
                    mma_f16(acc[mt][nt2 * 2 + 1],
                            ah[mt][0], ah[mt][1], ah[mt][2], ah[mt][3], bvv[2], bvv[3]);
                    mma_f16(acc[mt][nt2 * 2 + 1],
                            al[mt][0], al[mt][1], al[mt][2], al[mt][3], bvv[2], bvv[3]);
                }
            }
        }
    }
#undef LOADC

    // epilogue
#pragma unroll
    for (int mt = 0; mt < 2; mt++) {
#pragma unroll
        for (int half = 0; half < 2; half++) {
            const int row = mBase + wm * 32 + mt * 16 + g + half * 8;
            const int nseq = row & (SEQ - 1);
#pragma unroll
            for (int nt = 0; nt < 4; nt++) {
                const int col = nBase + wn * 32 + nt * 8 + tig * 2;
                float v0 = acc[mt][nt][half * 2 + 0] + __ldg(bias + col);
                float v1 = acc[mt][nt][half * 2 + 1] + __ldg(bias + col + 1);
                if (mode == 0) {
                    *(float2*)((float*)Cout + (size_t)row * EMB + col) =
                        make_float2(v0, v1);
                } else if (mode == 1) {
                    v0 = v0 / (1.f + expf(-v0));
                    v1 = v1 / (1.f + expf(-v1));
                    *(float2*)((float*)Cout + (size_t)row * EMB + col) =
                        make_float2(v0, v1);
                } else {
                    float x = v0, y = v1;
                    const int d = col & 63, head = col >> 6;
                    if (mode == 2 || mode == 3) {
                        const int p = d >> 1;
                        const float sv = g_sin[nseq * 32 + p];
                        const float cv = g_cos[nseq * 32 + p];
                        x = v0 * cv - v1 * sv;
                        y = v1 * cv + v0 * sv;
                        if (mode == 3) { x *= 0.125f; y *= 0.125f; }
                    }
                    __half* C = (__half*)Cout;
                    if (mode == 2) {   // Q: 2-term split
                        __half h0, l0, h1, l1;
                        hilo16(x, h0, l0);
                        hilo16(y, h1, l1);
                        const size_t base = (size_t)row * KA + head * 128 + d;
                        *(uint32_t*)(C + base)      = pk2h(h0, h1);
                        *(uint32_t*)(C + base + 64) = pk2h(l0, l1);
                    } else {           // K / V: single-term
                        const size_t base = (size_t)row * KW + head * 64 + d;
                        *(uint32_t*)(C + base) =
                            pk2h(__float2half_rn(x), __float2half_rn(y));
                    }
                }
            }
        }
    }
}

// ---------------------------------------------------------------------------
// Retention: Q 2-term [hi64|lo64], K/V single-term fp16; QK/SV 2-term with
// fragment reuse; S masked + split in registers in four 32-col quarters.
// 71 KB smem -> 2 CTAs/SM. (unchanged from round 11)
// ---------------------------------------------------------------------------
#define RT_P   272
#define RT_PK  144
#define RT_QS  0
#define RT_KS  34816
#define RT_VS  53248
#define RT_TAB 71680
#define RT_SMEM 72704

__global__ void __launch_bounds__(256, 2)
ret_k(const __half* __restrict__ Qb, const __half* __restrict__ Kb,
      const __half* __restrict__ Vb, const float* __restrict__ G,
      __half* __restrict__ X2)
{
    extern __shared__ char sm[];
    const uint32_t smb = smem_u32(sm);
    float* tab = (float*)(sm + RT_TAB);
    const int tid = threadIdx.x;
    const int lane = tid & 31, wid = tid >> 5;
    const int g = lane >> 2, tig = lane & 3;
    const int rb = (int)(gridDim.x - 1 - blockIdx.x);   // heavy tiles first
    const int rowBase = rb * 128;
    const int bh = blockIdx.y;
    const int b = bh >> 3, h = bh & 7;

    const int aRow   = lane & 15;
    const int aOff16 = (lane >> 4) * 16;
    const int bRow   = (lane & 7) + ((lane >> 4) << 3);
    const int bOff16 = ((lane >> 3) & 1) * 16;
    const int vRow   = (lane & 7) + (((lane >> 3) & 1) << 3);
    const int vCol16 = ((lane >> 4) & 1) * 16;
    const uint32_t vAddrBase = smb + RT_VS + vRow * RT_PK + vCol16;

    const double la = -3.4657359027997265;   // log(1/32)
    const double lb = -6.2383246250395075;   // log(1/512)
    const float gamma = (float)(1.0 - exp(la + (lb - la) * ((double)h / 7.0)));
    const float lg2g = log2f(gamma);
    if (tid < 256) tab[tid] = exp2f(lg2g * (float)(tid - 128));

    // Q tile: 128 rows x 128 fp16 ([hi64|lo64])
    {
        const __half* qs = Qb + (size_t)(b * SEQ + rowBase) * KA + h * 128;
        for (int e = tid; e < 128 * 16; e += 256) {
            int r = e >> 4, q = e & 15;
            *(uint4*)(sm + RT_QS + r * RT_P + q * 16) =
                *(const uint4*)(qs + (size_t)r * KA + q * 8);
        }
    }

    float sacc[8][4];
#pragma unroll
    for (int i = 0; i < 8; i++)
#pragma unroll
        for (int j = 0; j < 4; j++) sacc[i][j] = 0.f;

    const uint32_t qAddr = smb + RT_QS + (wid * 16 + aRow) * RT_P + aOff16;

    for (int sT = 0; sT <= rb; sT++) {
        const int colBase = sT * 128;
        __syncthreads();
        {
            const __half* ks = Kb + (size_t)(b * SEQ + colBase) * KW + h * 64;
            const __half* vs = Vb + (size_t)(b * SEQ + colBase) * KW + h * 64;
            for (int e = tid; e < 128 * 8; e += 256) {
                int r = e >> 3, q = e & 7;
                *(uint4*)(sm + RT_KS + r * RT_PK + q * 16) =
                    *(const uint4*)(ks + (size_t)r * KW + q * 8);
                *(uint4*)(sm + RT_VS + r * RT_PK + q * 16) =
                    *(const uint4*)(vs + (size_t)r * KW + q * 8);
            }
        }
        __syncthreads();

        const float basefac = exp2f(lg2g * (float)(rowBase - colBase));
        const bool diag = (sT == rb);
        const int li0 = wid * 16 + g;

#pragma unroll
        for (int qt = 0; qt < 4; qt++) {
            float qk[4][4];
#pragma unroll
            for (int i = 0; i < 4; i++)
#pragma unroll
                for (int j = 0; j < 4; j++) qk[i][j] = 0.f;

#pragma unroll
            for (int ks = 0; ks < 4; ks++) {
                uint32_t aH[4], aL[4];
                ldsm4(aH, qAddr + ks * 32);
                ldsm4(aL, qAddr + 128 + ks * 32);
#pragma unroll
                for (int nt2 = 0; nt2 < 2; nt2++) {
                    uint32_t bvv[4];
                    ldsm4(bvv, smb + RT_KS
                          + (qt * 32 + nt2 * 16 + bRow) * RT_PK + ks * 32 + bOff16);
                    mma_f16(qk[nt2 * 2 + 0], aH[0], aH[1], aH[2], aH[3], bvv[0], bvv[1]);
                    mma_f16(qk[nt2 * 2 + 0], aL[0], aL[1], aL[2], aL[3], bvv[0], bvv[1]);
                    mma_f16(qk[nt2 * 2 + 1], aH[0], aH[1], aH[2], aH[3], bvv[2], bvv[3]);
                    mma_f16(qk[nt2 * 2 + 1], aL[0], aL[1], aL[2], aL[3], bvv[2], bvv[3]);
                }
            }

            uint32_t sh01[4], sl01[4], sh23[4], sl23[4];
#pragma unroll
            for (int nt = 0; nt < 4; nt++) {
                const int lj = qt * 32 + nt * 8 + tig * 2;
                const int d00 = li0 - lj,     d01 = d00 - 1;
                const int d10 = li0 + 8 - lj, d11 = d10 - 1;
                float w00 = basefac * tab[d00 + 128];
                float w01 = basefac * tab[d01 + 128];
                float w10 = basefac * tab[d10 + 128];
                float w11 = basefac * tab[d11 + 128];
                if (diag && d00 < 0) w00 = 0.f;
                if (diag && d01 < 0) w01 = 0.f;
                if (diag && d10 < 0) w10 = 0.f;
                if (diag && d11 < 0) w11 = 0.f;
                const float m00 = qk[nt][0] * w00, m01 = qk[nt][1] * w01;
                const float m10 = qk[nt][2] * w10, m11 = qk[nt][3] * w11;
                __half h00, l00, h01, l01, h10, l10, h11, l11;
                hilo16(m00, h00, l00); hilo16(m01, h01, l01);
                hilo16(m10, h10, l10); hilo16(m11, h11, l11);
                sh01[nt] = pk2h(h00, h01); sl01[nt] = pk2h(l00, l01);
                sh23[nt] = pk2h(h10, h11); sl23[nt] = pk2h(l10, l11);
            }

#pragma unroll
            for (int ksl = 0; ksl < 2; ksl++) {
                uint32_t ah[4] = {sh01[2 * ksl], sh23[2 * ksl],
                                  sh01[2 * ksl + 1], sh23[2 * ksl + 1]};
                uint32_t al[4] = {sl01[2 * ksl], sl23[2 * ksl],
                                  sl01[2 * ksl + 1], sl23[2 * ksl + 1]};
                const uint32_t vRowAddr = vAddrBase + (qt * 2 + ksl) * 16 * RT_PK;
#pragma unroll
                for (int dt = 0; dt < 4; dt++) {
                    uint32_t bhv[4];
                    ldsm4t(bhv, vRowAddr + dt * 32);
                    mma_f16(sacc[dt * 2 + 0], ah[0], ah[1], ah[2], ah[3], bhv[0], bhv[1]);
                    mma_f16(sacc[dt * 2 + 0], al[0], al[1], al[2], al[3], bhv[0], bhv[1]);
                    mma_f16(sacc[dt * 2 + 1], ah[0], ah[1], ah[2], ah[3], bhv[2], bhv[3]);
                    mma_f16(sacc[dt * 2 + 1], al[0], al[1], al[2], al[3], bhv[2], bhv[3]);
                }
            }
        }
    }

    // GroupNorm over d=64 per row + gate + fp16 split store
    float s1a = 0.f, s2a = 0.f, s1b = 0.f, s2b = 0.f;
#pragma unroll
    for (int nt = 0; nt < 8; nt++) {
        s1a += sacc[nt][0] + sacc[nt][1];
        s2a += sacc[nt][0] * sacc[nt][0] + sacc[nt][1] * sacc[nt][1];
        s1b += sacc[nt][2] + sacc[nt][3];
        s2b += sacc[nt][2] * sacc[nt][2] + sacc[nt][3] * sacc[nt][3];
    }
#pragma unroll
    for (int m = 1; m <= 2; m <<= 1) {
        s1a += __shfl_xor_sync(0xffffffffu, s1a, m);
        s2a += __shfl_xor_sync(0xffffffffu, s2a, m);
        s1b += __shfl_xor_sync(0xffffffffu, s1b, m);
        s2b += __shfl_xor_sync(0xffffffffu, s2b, m);
    }
    const float meanA = s1a * (1.f / 64.f);
    const float meanB = s1b * (1.f / 64.f);
    float varA = fmaxf(s2a * (1.f / 64.f) - meanA * meanA, 0.f);
    float varB = fmaxf(s2b * (1.f / 64.f) - meanB * meanB, 0.f);
    const float invA = rsqrtf(varA + 1e-6f);
    const float invB = rsqrtf(varB + 1e-6f);

    const int mrowA = b * SEQ + rowBase + wid * 16 + g;
    const int mrowB = mrowA + 8;
#pragma unroll
    for (int nt = 0; nt < 8; nt++) {
        const int d = nt * 8 + tig * 2;
        const float2 ga = *(const float2*)(G + (size_t)mrowA * EMB + h * 64 + d);
        const float2 gb = *(const float2*)(G + (size_t)mrowB * EMB + h * 64 + d);
        float xa0 = (sacc[nt][0] - meanA) * invA * ga.x;
        float xa1 = (sacc[nt][1] - meanA) * invA * ga.y;
        float xb0 = (sacc[nt][2] - meanB) * invB * gb.x;
        float xb1 = (sacc[nt][3] - meanB) * invB * gb.y;
        __half h0, l0, h1, l1;
        hilo16(xa0, h0, l0);
        hilo16(xa1, h1, l1);
        {
            const size_t base = (size_t)mrowA * KA + h * 128 + d;
            *(uint32_t*)(X2 + base)      = pk2h(h0, h1);
            *(uint32_t*)(X2 + base + 64) = pk2h(l0, l1);
        }
        hilo16(xb0, h0, l0);
        hilo16(xb1, h1, l1);
        {
            const size_t base = (size_t)mrowB * KA + h * 128 + d;
            *(uint32_t*)(X2 + base)      = pk2h(h0, h1);
            *(uint32_t*)(X2 + base + 64) = pk2h(l0, l1);
        }
    }
}

// ---------------------------------------------------------------------------
// Launch
// ---------------------------------------------------------------------------
extern "C" void kernel_launch(void* const* d_in, const int* in_sizes, int n_in,
                              void* d_out, int out_size)
{
    (void)in_sizes; (void)n_in; (void)out_size;
    const float* query = (const float*)d_in[0];
    const float* kin   = (const float*)d_in[1];
    const float* vin   = (const float*)d_in[2];
    const float* Wq = (const float*)d_in[3];  const float* bq = (const float*)d_in[4];
    const float* Wk = (const float*)d_in[5];  const float* bk = (const float*)d_in[6];
    const float* Wv = (const float*)d_in[7];  const float* bv = (const float*)d_in[8];
    const float* Wg = (const float*)d_in[9];  const float* bg = (const float*)d_in[10];
    const float* Wo = (const float*)d_in[11]; const float* bo = (const float*)d_in[12];
    float* out = (float*)d_out;

    float *Gf, *sinp, *cosp;
    __half *bA1, *bA2, *bA3, *bW, *Qb, *Kb, *Vb, *bX2;
    cudaGetSymbolAddress((void**)&bA1, g_bA1);
    cudaGetSymbolAddress((void**)&bA2, g_bA2);
    cudaGetSymbolAddress((void**)&bA3, g_bA3);
    cudaGetSymbolAddress((void**)&bW,  g_bW);
    cudaGetSymbolAddress((void**)&Qb,  g_Qb);
    cudaGetSymbolAddress((void**)&Kb,  g_Kb);
    cudaGetSymbolAddress((void**)&Vb,  g_Vb);
    cudaGetSymbolAddress((void**)&Gf,  g_G);
    cudaGetSymbolAddress((void**)&bX2, g_bX2);
    cudaGetSymbolAddress((void**)&sinp, g_sin);
    cudaGetSymbolAddress((void**)&cosp, g_cos);

    cudaFuncSetAttribute(proj_all, cudaFuncAttributeMaxDynamicSharedMemorySize, PJ_SMEM);
    cudaFuncSetAttribute(ret_k, cudaFuncAttributeMaxDynamicSharedMemorySize, RT_SMEM);

    rope_k<<<256, 256>>>(sinp, cosp);

    dim3 ca((MROWS * 128 + 255) / 256, 3);
    convA_k<<<ca, 256>>>(query, kin, vin, bA1, bA2, bA3);
    dim3 cw((EMB * 128 + 255) / 256, 5);
    convW_k<<<cw, 256>>>(Wq, Wk, Wv, Wg, Wo, bW);

    dim3 pg4(EMB / 64, MROWS / 128, 4);   // (8, 32, 4) = 1024 CTAs
    proj_all<<<pg4, 256, PJ_SMEM>>>(bA1, bA2, bA3, bX2, bW,
                                    bq, bk, bv, bg, bo,
                                    Qb, Kb, Vb, Gf, out, 0);

    dim3 rg(SEQ / 128, BATCH * HEADS);  // (16, 16)
    ret_k<<<rg, 256, RT_SMEM>>>(Qb, Kb, Vb, Gf, bX2);

    dim3 pg1(EMB / 64, MROWS / 128, 1);
    proj_all<<<pg1, 256, PJ_SMEM>>>(bA1, bA2, bA3, bX2, bW,
                                    bq, bk, bv, bg, bo,
                                    Qb, Kb, Vb, Gf, out, 1);
}

// round 13
// speedup vs baseline: 1.1421x; 1.1421x over previous
#include <cuda_runtime.h>
#include <cuda_fp16.h>
#include <math.h>
#include <stdint.h>

#define BATCH 2
#define SEQ   2048
#define EMB   512
#define HEADS 8
#define HDIM  64
#define MROWS 4096
#define KA    1024   // split activations: 8 blocks of [hi64|lo64] (fp16)
#define KW    512    // weights: single-term fp16

// ---------------------------------------------------------------------------
// Scratch (device globals; allocation in kernel_launch is forbidden)
// ---------------------------------------------------------------------------
__device__ __align__(16) __half g_bA1[MROWS * KA];    // query split
__device__ __align__(16) __half g_bA2[MROWS * KA];    // k input split
__device__ __align__(16) __half g_bA3[MROWS * KA];    // v input split
__device__ __align__(16) __half g_bW [5 * EMB * KW];  // weights (hi only)
__device__ __align__(16) __half g_Qb [MROWS * KA];    // per-head [hi64|lo64]
__device__ __align__(16) __half g_Kb [MROWS * KW];    // per-head hi64
__device__ __align__(16) __half g_Vb [MROWS * KW];    // per-head hi64
__device__ __align__(16) float  g_G  [MROWS * EMB];   // silu gate fp32
__device__ __align__(16) __half g_bX2[MROWS * KA];    // retention out split
__device__ __align__(16) float  g_part[2 * MROWS * EMB];  // ret partial sums
__device__ __align__(16) float g_sin[SEQ * 32];
__device__ __align__(16) float g_cos[SEQ * 32];

// ---------------------------------------------------------------------------
// Helpers
// ---------------------------------------------------------------------------
__device__ __forceinline__ uint32_t smem_u32(const void* p) {
    uint32_t a;
    asm("{ .reg .u64 t; cvta.to.shared.u64 t, %1; cvt.u32.u64 %0, t; }"
        : "=r"(a) : "l"(p));
    return a;
}

__device__ __forceinline__ void mma_f16(float* c, uint32_t a0, uint32_t a1,
                                        uint32_t a2, uint32_t a3,
                                        uint32_t b0, uint32_t b1) {
    asm volatile(
        "mma.sync.aligned.m16n8k16.row.col.f32.f16.f16.f32 "
        "{%0,%1,%2,%3}, {%4,%5,%6,%7}, {%8,%9}, {%0,%1,%2,%3};\n"
        : "+f"(c[0]), "+f"(c[1]), "+f"(c[2]), "+f"(c[3])
        : "r"(a0), "r"(a1), "r"(a2), "r"(a3), "r"(b0), "r"(b1));
}

__device__ __forceinline__ void ldsm4(uint32_t* r, uint32_t addr) {
    asm volatile("ldmatrix.sync.aligned.m8n8.x4.shared.b16 {%0,%1,%2,%3}, [%4];"
                 : "=r"(r[0]), "=r"(r[1]), "=r"(r[2]), "=r"(r[3]) : "r"(addr));
}
__device__ __forceinline__ void ldsm4t(uint32_t* r, uint32_t addr) {
    asm volatile("ldmatrix.sync.aligned.m8n8.x4.trans.shared.b16 {%0,%1,%2,%3}, [%4];"
                 : "=r"(r[0]), "=r"(r[1]), "=r"(r[2]), "=r"(r[3]) : "r"(addr));
}

#define CP16(dst, src) \
    asm volatile("cp.async.cg.shared.global [%0], [%1], 16;" \
                 :: "r"((uint32_t)(dst)), "l"(src))
#define CP_COMMIT() asm volatile("cp.async.commit_group;" ::: "memory")
#define CP_WAIT0()  asm volatile("cp.async.wait_group 0;" ::: "memory")

__device__ __forceinline__ void hilo16(float x, __half& h, __half& l) {
    h = __float2half_rn(x);
    l = __float2half_rn(x - __half2float(h));
}
__device__ __forceinline__ uint32_t pk2h(__half a, __half b) {
    uint16_t lo = *(uint16_t*)&a, hi = *(uint16_t*)&b;
    return (uint32_t)lo | ((uint32_t)hi << 16);
}

// ---------------------------------------------------------------------------
// Rotary tables
// ---------------------------------------------------------------------------
__global__ void rope_k(float* __restrict__ st, float* __restrict__ ct) {
    int i = blockIdx.x * blockDim.x + threadIdx.x;
    if (i >= SEQ * 32) return;
    int n = i >> 5, p = i & 31;
    float theta = powf(10000.f, -(float)p * (1.0f / 31.0f));
    float sv, cv;
    sincosf((float)n * theta, &sv, &cv);
    st[i] = sv;
    ct[i] = cv;
}

// ---------------------------------------------------------------------------
// fp32 -> fp16 splits. Activations: [hi64|lo64] blocks; weights: hi only.
// ---------------------------------------------------------------------------
__device__ __forceinline__ void splitA4(const float* __restrict__ src,
                                        __half* __restrict__ dst, int idx) {
    int row = idx >> 7, c = (idx & 127) << 2;
    float4 v = *(const float4*)(src + (size_t)row * EMB + c);
    float x[4] = {v.x, v.y, v.z, v.w};
    __half h[4], l[4];
#pragma unroll
    for (int i = 0; i < 4; i++) hilo16(x[i], h[i], l[i]);
    uint2 hp, lp;
    hp.x = pk2h(h[0], h[1]); hp.y = pk2h(h[2], h[3]);
    lp.x = pk2h(l[0], l[1]); lp.y = pk2h(l[2], l[3]);
    size_t base = (size_t)row * KA + (c >> 6) * 128 + (c & 63);
    *(uint2*)(dst + base)      = hp;
    *(uint2*)(dst + base + 64) = lp;
}
__device__ __forceinline__ void splitW4(const float* __restrict__ src,
                                        __half* __restrict__ dst, int idx) {
    int row = idx >> 7, c = (idx & 127) << 2;
    float4 v = *(const float4*)(src + (size_t)row * EMB + c);
    __half h[4];
    h[0] = __float2half_rn(v.x); h[1] = __float2half_rn(v.y);
    h[2] = __float2half_rn(v.z); h[3] = __float2half_rn(v.w);
    uint2 hp;
    hp.x = pk2h(h[0], h[1]); hp.y = pk2h(h[2], h[3]);
    *(uint2*)(dst + (size_t)row * KW + c) = hp;
}

__global__ void convA_k(const float* __restrict__ s0, const float* __restrict__ s1,
                        const float* __restrict__ s2,
                        __half* __restrict__ d0, __half* __restrict__ d1,
                        __half* __restrict__ d2) {
    int idx = blockIdx.x * blockDim.x + threadIdx.x;
    if (idx >= MROWS * 128) return;
    const float* src; __half* dst;
    if (blockIdx.y == 0)      { src = s0; dst = d0; }
    else if (blockIdx.y == 1) { src = s1; dst = d1; }
    else                      { src = s2; dst = d2; }
    splitA4(src, dst, idx);
}

__global__ void convW_k(const float* __restrict__ s0, const float* __restrict__ s1,
                        const float* __restrict__ s2, const float* __restrict__ s3,
                        const float* __restrict__ s4, __half* __restrict__ dst) {
    int idx = blockIdx.x * blockDim.x + threadIdx.x;
    if (idx >= EMB * 128) return;
    const float* src;
    switch (blockIdx.y) {
        case 0: src = s0; break;
        case 1: src = s1; break;
        case 2: src = s2; break;
        case 3: src = s3; break;
        default: src = s4; break;
    }
    splitW4(src, dst + (size_t)blockIdx.y * EMB * KW, idx);
}

// ---------------------------------------------------------------------------
// Projection GEMM (merged) — round-11 version (CTA 128x128, warp 32x64).
// phase 0: z=0 Q(rotary,split), z=1 K(rotary*.125,hi), z=2 V(hi), z=3 G(silu)
// phase 1: output projection (fp32 out)
// ---------------------------------------------------------------------------
#define PJ_PA 272
#define PJ_PW 144
#define PJ_A0 0
#define PJ_W0 69632
#define PJ_SMEM 106496
#define PJ_CHUNKS 8

__global__ void __launch_bounds__(256, 2)
proj_all(const __half* __restrict__ bA1, const __half* __restrict__ bA2,
         const __half* __restrict__ bA3, const __half* __restrict__ bX2,
         const __half* __restrict__ bW,
         const float* __restrict__ bq, const float* __restrict__ bk,
         const float* __restrict__ bv, const float* __restrict__ bg,
         const float* __restrict__ bo,
         __half* __restrict__ Qb, __half* __restrict__ Kb,
         __half* __restrict__ Vb, float* __restrict__ Gf,
         float* __restrict__ outp, int phase)
{
    extern __shared__ char sm[];
    const uint32_t smb = smem_u32(sm);
    const int tid = threadIdx.x;
    const int lane = tid & 31, wid = tid >> 5;
    const int g = lane >> 2, tig = lane & 3;
    const int wm = wid >> 1, wn = wid & 1;
    const int mBase = blockIdx.y * 128, nBase = blockIdx.x * 128;
    const int z = blockIdx.z;

    const __half* A;
    const float* bias;
    int mode;
    void* Cout;
    const size_t wOff = (size_t)EMB * KW;
    const __half* W;
    if (phase == 0) {
        if (z == 0)      { A = bA1; W = bW;            bias = bq; mode = 2; Cout = Qb; }
        else if (z == 1) { A = bA2; W = bW + 1 * wOff; bias = bk; mode = 3; Cout = Kb; }
        else if (z == 2) { A = bA3; W = bW + 2 * wOff; bias = bv; mode = 4; Cout = Vb; }
        else             { A = bA1; W = bW + 3 * wOff; bias = bg; mode = 1; Cout = Gf; }
    } else {
        A = bX2; W = bW + 4 * wOff; bias = bo; mode = 0; Cout = outp;
    }

    const int aRow   = lane & 15;
    const int aOff16 = (lane >> 4) * 16;
    const int bRow   = (lane & 7) + ((lane >> 4) << 3);
    const int bOff16 = ((lane >> 3) & 1) * 16;

    float acc[2][8][4];
#pragma unroll
    for (int a = 0; a < 2; a++)
#pragma unroll
        for (int b = 0; b < 8; b++)
#pragma unroll
            for (int c = 0; c < 4; c++) acc[a][b][c] = 0.f;

    const int crow = tid >> 1;
    const int csel = tid & 1;
    const __half* Arow = A + (size_t)(mBase + crow) * KA;
    const __half* Wrow = W + (size_t)(nBase + crow) * KW;

#define LOADC(c) do {                                                         \
    const int _b = (c) & 1;                                                   \
    const uint32_t _ad = smb + PJ_A0 + _b * 34816 + crow * PJ_PA + csel * 128;\
    const __half* _as = Arow + (c) * 128 + csel * 64;                         \
    _Pragma("unroll")                                                         \
    for (int _i = 0; _i < 8; _i++) CP16(_ad + _i * 16, _as + _i * 8);         \
    const uint32_t _wd = smb + PJ_W0 + _b * 18432 + crow * PJ_PW + csel * 64; \
    const __half* _ws = Wrow + (c) * 64 + csel * 32;                          \
    _Pragma("unroll")                                                         \
    for (int _i = 0; _i < 4; _i++) CP16(_wd + _i * 16, _ws + _i * 8);         \
} while (0)

    LOADC(0);
    CP_COMMIT();

    for (int c = 0; c < PJ_CHUNKS; c++) {
        CP_WAIT0();
        __syncthreads();
        if (c + 1 < PJ_CHUNKS) {
            LOADC(c + 1);
            CP_COMMIT();
        }
        const uint32_t aS = smb + PJ_A0 + (c & 1) * 34816;
        const uint32_t wS = smb + PJ_W0 + (c & 1) * 18432;
#pragma unroll
        for (int ks = 0; ks < 4; ks++) {
            uint32_t ah[2][4], al[2][4];
#pragma unroll
            for (int mt = 0; mt < 2; mt++) {
                const uint32_t ar = aS + (wm * 32 + mt * 16 + aRow) * PJ_PA;
                ldsm4(ah[mt], ar + ks * 32 + aOff16);
                ldsm4(al[mt], ar + 128 + ks * 32 + aOff16);
            }
#pragma unroll
            for (int nt2 = 0; nt2 < 4; nt2++) {
                uint32_t bvv[4];
                ldsm4(bvv, wS + (wn * 64 + nt2 * 16 + bRow) * PJ_PW
                           + ks * 32 + bOff16);
#pragma unroll
                for (int mt = 0; mt < 2; mt++) {
                    mma_f16(acc[mt][nt2 * 2 + 0],
                            ah[mt][0], ah[mt][1], ah[mt][2], ah[mt][3], bvv[0], bvv[1]);
                    mma_f16(acc[mt][nt2 * 2 + 0],
                            al[mt][0], al[mt][1], al[mt][2], al[mt][3], bvv[0], bvv[1]);
                    mma_f16(acc[mt][nt2 * 2 + 1],
                            ah[mt][0], ah[mt][1], ah[mt][2], ah[mt][3], bvv[2], bvv[3]);
                    mma_f16(acc[mt][nt2 * 2 + 1],
                            al[mt][0], al[mt][1], al[mt][2], al[mt][3], bvv[2], bvv[3]);
                }
            }
        }
    }
#undef LOADC

    // epilogue
#pragma unroll
    for (int mt = 0; mt < 2; mt++) {
#pragma unroll
        for (int half = 0; half < 2; half++) {
            const int row = mBase + wm * 32 + mt * 16 + g + half * 8;
            const int nseq = row & (SEQ - 1);
#pragma unroll
            for (int nt = 0; nt < 8; nt++) {
                const int col = nBase + wn * 64 + nt * 8 + tig * 2;
                float v0 = acc[mt][nt][half * 2 + 0] + __ldg(bias + col);
                float v1 = acc[mt][nt][half * 2 + 1] + __ldg(bias + col + 1);
                if (mode == 0) {
                    *(float2*)((float*)Cout + (size_t)row * EMB + col) =
                        make_float2(v0, v1);
                } else if (mode == 1) {
                    v0 = v0 / (1.f + expf(-v0));
                    v1 = v1 / (1.f + expf(-v1));
                    *(float2*)((float*)Cout + (size_t)row * EMB + col) =
                        make_float2(v0, v1);
                } else {
                    float x = v0, y = v1;
                    const int d = col & 63, head = col >> 6;
                    if (mode == 2 || mode == 3) {
                        const int p = d >> 1;
                        const float sv = g_sin[nseq * 32 + p];
                        const float cv = g_cos[nseq * 32 + p];
                        x = v0 * cv - v1 * sv;
                        y = v1 * cv + v0 * sv;
                        if (mode == 3) { x *= 0.125f; y *= 0.125f; }
                    }
                    __half* C = (__half*)Cout;
                    if (mode == 2) {   // Q: 2-term split
                        __half h0, l0, h1, l1;
                        hilo16(x, h0, l0);
                        hilo16(y, h1, l1);
                        const size_t base = (size_t)row * KA + head * 128 + d;
                        *(uint32_t*)(C + base)      = pk2h(h0, h1);
                        *(uint32_t*)(C + base + 64) = pk2h(l0, l1);
                    } else {           // K / V: single-term
                        const size_t base = (size_t)row * KW + head * 64 + d;
                        *(uint32_t*)(C + base) =
                            pk2h(__float2half_rn(x), __float2half_rn(y));
                    }
                }
            }
        }
    }
}

// ---------------------------------------------------------------------------
// Retention with split-K over the s-range for load balance:
// grid (32, 16): x -> (rb = 15 - (x>>1), shalf = x&1). shalf 0 processes
// s-tiles [0, n0), shalf 1 [n0, rb+1) with n0 = ceil((rb+1)/2). Raw fp32
// partial sums go to g_part; ret_fin reduces + GroupNorm + gate + split.
// ---------------------------------------------------------------------------
#define RT_P   272
#define RT_PK  144
#define RT_QS  0
#define RT_KS  34816
#define RT_VS  53248
#define RT_TAB 71680
#define RT_SMEM 72704

__global__ void __launch_bounds__(256, 2)
ret_k(const __half* __restrict__ Qb, const __half* __restrict__ Kb,
      const __half* __restrict__ Vb, float* __restrict__ P)
{
    extern __shared__ char sm[];
    const uint32_t smb = smem_u32(sm);
    float* tab = (float*)(sm + RT_TAB);
    const int tid = threadIdx.x;
    const int lane = tid & 31, wid = tid >> 5;
    const int g = lane >> 2, tig = lane & 3;
    const int rb = 15 - ((int)blockIdx.x >> 1);   // heavy tiles first
    const int shalf = blockIdx.x & 1;
    const int rowBase = rb * 128;
    const int bh = blockIdx.y;
    const int b = bh >> 3, h = bh & 7;

    const int n0 = (rb + 2) >> 1;                 // ceil((rb+1)/2)
    const int s0 = shalf ? n0 : 0;
    const int s1 = shalf ? (rb + 1) : n0;

    const int aRow   = lane & 15;
    const int aOff16 = (lane >> 4) * 16;
    const int bRow   = (lane & 7) + ((lane >> 4) << 3);
    const int bOff16 = ((lane >> 3) & 1) * 16;
    const int vRow   = (lane & 7) + (((lane >> 3) & 1) << 3);
    const int vCol16 = ((lane >> 4) & 1) * 16;
    const uint32_t vAddrBase = smb + RT_VS + vRow * RT_PK + vCol16;

    const double la = -3.4657359027997265;   // log(1/32)
    const double lb = -6.2383246250395075;   // log(1/512)
    const float gamma = (float)(1.0 - exp(la + (lb - la) * ((double)h / 7.0)));
    const float lg2g = log2f(gamma);
    if (tid < 256) tab[tid] = exp2f(lg2g * (float)(tid - 128));

    // Q tile: 128 rows x 128 fp16 ([hi64|lo64])
    if (s0 < s1) {
        const __half* qs = Qb + (size_t)(b * SEQ + rowBase) * KA + h * 128;
        for (int e = tid; e < 128 * 16; e += 256) {
            int r = e >> 4, q = e & 15;
            *(uint4*)(sm + RT_QS + r * RT_P + q * 16) =
                *(const uint4*)(qs + (size_t)r * KA + q * 8);
        }
    }

    float sacc[8][4];
#pragma unroll
    for (int i = 0; i < 8; i++)
#pragma unroll
        for (int j = 0; j < 4; j++) sacc[i][j] = 0.f;

    const uint32_t qAddr = smb + RT_QS + (wid * 16 + aRow) * RT_P + aOff16;

    for (int sT = s0; sT < s1; sT++) {
        const int colBase = sT * 128;
        __syncthreads();
        {
            const __half* ks = Kb + (size_t)(b * SEQ + colBase) * KW + h * 64;
            const __half* vs = Vb + (size_t)(b * SEQ + colBase) * KW + h * 64;
            for (int e = tid; e < 128 * 8; e += 256) {
                int r = e >> 3, q = e & 7;
                *(uint4*)(sm + RT_KS + r * RT_PK + q * 16) =
                    *(const uint4*)(ks + (size_t)r * KW + q * 8);
                *(uint4*)(sm + RT_VS + r * RT_PK + q * 16) =
                    *(const uint4*)(vs + (size_t)r * KW + q * 8);
            }
        }
        __syncthreads();

        const float basefac = exp2f(lg2g * (float)(rowBase - colBase));
        const bool diag = (sT == rb);
        const int li0 = wid * 16 + g;

#pragma unroll
        for (int qt = 0; qt < 4; qt++) {
            float qk[4][4];
#pragma unroll
            for (int i = 0; i < 4; i++)
#pragma unroll
                for (int j = 0; j < 4; j++) qk[i][j] = 0.f;

#pragma unroll
            for (int ks = 0; ks < 4; ks++) {
                uint32_t aH[4], aL[4];
                ldsm4(aH, qAddr + ks * 32);
                ldsm4(aL, qAddr + 128 + ks * 32);
#pragma unroll
                for (int nt2 = 0; nt2 < 2; nt2++) {
                    uint32_t bvv[4];
                    ldsm4(bvv, smb + RT_KS
                          + (qt * 32 + nt2 * 16 + bRow) * RT_PK + ks * 32 + bOff16);
                    mma_f16(qk[nt2 * 2 + 0], aH[0], aH[1], aH[2], aH[3], bvv[0], bvv[1]);
                    mma_f16(qk[nt2 * 2 + 0], aL[0], aL[1], aL[2], aL[3], bvv[0], bvv[1]);
                    mma_f16(qk[nt2 * 2 + 1], aH[0], aH[1], aH[2], aH[3], bvv[2], bvv[3]);
                    mma_f16(qk[nt2 * 2 + 1], aL[0], aL[1], aL[2], aL[3], bvv[2], bvv[3]);
                }
            }

            uint32_t sh01[4], sl01[4], sh23[4], sl23[4];
#pragma unroll
            for (int nt = 0; nt < 4; nt++) {
                const int lj = qt * 32 + nt * 8 + tig * 2;
                const int d00 = li0 - lj,     d01 = d00 - 1;
                const int d10 = li0 + 8 - lj, d11 = d10 - 1;
                float w00 = basefac * tab[d00 + 128];
                float w01 = basefac * tab[d01 + 128];
                float w10 = basefac * tab[d10 + 128];
                float w11 = basefac * tab[d11 + 128];
                if (diag && d00 < 0) w00 = 0.f;
                if (diag && d01 < 0) w01 = 0.f;
                if (diag && d10 < 0) w10 = 0.f;
                if (diag && d11 < 0) w11 = 0.f;
                const float m00 = qk[nt][0] * w00, m01 = qk[nt][1] * w01;
                const float m10 = qk[nt][2] * w10, m11 = qk[nt][3] * w11;
                __half h00, l00, h01, l01, h10, l10, h11, l11;
                hilo16(m00, h00, l00); hilo16(m01, h01, l01);
                hilo16(m10, h10, l10); hilo16(m11, h11, l11);
                sh01[nt] = pk2h(h00, h01); sl01[nt] = pk2h(l00, l01);
                sh23[nt] = pk2h(h10, h11); sl23[nt] = pk2h(l10, l11);
            }

#pragma unroll
            for (int ksl = 0; ksl < 2; ksl++) {
                uint32_t ah[4] = {sh01[2 * ksl], sh23[2 * ksl],
                                  sh01[2 * ksl + 1], sh23[2 * ksl + 1]};
                uint32_t al[4] = {sl01[2 * ksl], sl23[2 * ksl],
                                  sl01[2 * ksl + 1], sl23[2 * ksl + 1]};
                const uint32_t vRowAddr = vAddrBase + (qt * 2 + ksl) * 16 * RT_PK;
#pragma unroll
                for (int dt = 0; dt < 4; dt++) {
                    uint32_t bhv[4];
                    ldsm4t(bhv, vRowAddr + dt * 32);
                    mma_f16(sacc[dt * 2 + 0], ah[0], ah[1], ah[2], ah[3], bhv[0], bhv[1]);
                    mma_f16(sacc[dt * 2 + 0], al[0], al[1], al[2], al[3], bhv[0], bhv[1]);
                    mma_f16(sacc[dt * 2 + 1], ah[0], ah[1], ah[2], ah[3], bhv[2], bhv[3]);
                    mma_f16(sacc[dt * 2 + 1], al[0], al[1], al[2], al[3], bhv[2], bhv[3]);
                }
            }
        }
    }

    // write raw fp32 partial sums (zeros if this half had no s-range)
    float* P0 = P + (size_t)shalf * (MROWS * EMB);
    const int mrowA = b * SEQ + rowBase + wid * 16 + g;
    const int mrowB = mrowA + 8;
#pragma unroll
    for (int nt = 0; nt < 8; nt++) {
        const int d = nt * 8 + tig * 2;
        *(float2*)(P0 + (size_t)mrowA * EMB + h * 64 + d) =
            make_float2(sacc[nt][0], sacc[nt][1]);
        *(float2*)(P0 + (size_t)mrowB * EMB + h * 64 + d) =
            make_float2(sacc[nt][2], sacc[nt][3]);
    }
}

// ---------------------------------------------------------------------------
// Reduce partials + GroupNorm + gate + fp16 split store. One warp per (row,h).
// ---------------------------------------------------------------------------
__global__ void __launch_bounds__(256)
ret_fin(const float* __restrict__ P, const float* __restrict__ G,
        __half* __restrict__ X2)
{
    const int w = blockIdx.x * 8 + (threadIdx.x >> 5);
    const int lane = threadIdx.x & 31;
    const int mrow = w >> 3, h = w & 7;
    const size_t base = (size_t)mrow * EMB + h * 64 + lane * 2;

    const float2 a = *(const float2*)(P + base);
    const float2 b2 = *(const float2*)(P + (size_t)MROWS * EMB + base);
    const float x0 = a.x + b2.x;
    const float x1 = a.y + b2.y;

    float s1 = x0 + x1;
    float s2 = x0 * x0 + x1 * x1;
#pragma unroll
    for (int m = 16; m >= 1; m >>= 1) {
        s1 += __shfl_xor_sync(0xffffffffu, s1, m);
        s2 += __shfl_xor_sync(0xffffffffu, s2, m);
    }
    const float mean = s1 * (1.f / 64.f);
    float var = fmaxf(s2 * (1.f / 64.f) - mean * mean, 0.f);
    const float inv = rsqrtf(var + 1e-6f);

    const float2 gg = *(const float2*)(G + base);
    const float y0 = (x0 - mean) * inv * gg.x;
    const float y1 = (x1 - mean) * inv * gg.y;

    __half h0, l0, h1, l1;
    hilo16(y0, h0, l0);
    hilo16(y1, h1, l1);
    const size_t ob = (size_t)mrow * KA + h * 128 + lane * 2;
    *(uint32_t*)(X2 + ob)      = pk2h(h0, h1);
    *(uint32_t*)(X2 + ob + 64) = pk2h(l0, l1);
}

// ---------------------------------------------------------------------------
// Launch
// ---------------------------------------------------------------------------
extern "C" void kernel_launch(void* const* d_in, const int* in_sizes, int n_in,
                              void* d_out, int out_size)
{
    (void)in_sizes; (void)n_in; (void)out_size;
    const float* query = (const float*)d_in[0];
    const float* kin   = (const float*)d_in[1];
    const float* vin   = (const float*)d_in[2];
    const float* Wq = (const float*)d_in[3];  const float* bq = (const float*)d_in[4];
    const float* Wk = (const float*)d_in[5];  const float* bk = (const float*)d_in[6];
    const float* Wv = (const float*)d_in[7];  const float* bv = (const float*)d_in[8];
    const float* Wg = (const float*)d_in[9];  const float* bg = (const float*)d_in[10];
    const float* Wo = (const float*)d_in[11]; const float* bo = (const float*)d_in[12];
    float* out = (float*)d_out;

    float *Gf, *sinp, *cosp, *Pp;
    __half *bA1, *bA2, *bA3, *bW, *Qb, *Kb, *Vb, *bX2;
    cudaGetSymbolAddress((void**)&bA1, g_bA1);
    cudaGetSymbolAddress((void**)&bA2, g_bA2);
    cudaGetSymbolAddress((void**)&bA3, g_bA3);
    cudaGetSymbolAddress((void**)&bW,  g_bW);
    cudaGetSymbolAddress((void**)&Qb,  g_Qb);
    cudaGetSymbolAddress((void**)&Kb,  g_Kb);
    cudaGetSymbolAddress((void**)&Vb,  g_Vb);
    cudaGetSymbolAddress((void**)&Gf,  g_G);
    cudaGetSymbolAddress((void**)&bX2, g_bX2);
    cudaGetSymbolAddress((void**)&Pp,  g_part);
    cudaGetSymbolAddress((void**)&sinp, g_sin);
    cudaGetSymbolAddress((void**)&cosp, g_cos);

    cudaFuncSetAttribute(proj_all, cudaFuncAttributeMaxDynamicSharedMemorySize, PJ_SMEM);
    cudaFuncSetAttribute(ret_k, cudaFuncAttributeMaxDynamicSharedMemorySize, RT_SMEM);

    rope_k<<<256, 256>>>(sinp, cosp);

    dim3 ca((MROWS * 128 + 255) / 256, 3);
    convA_k<<<ca, 256>>>(query, kin, vin, bA1, bA2, bA3);
    dim3 cw((EMB * 128 + 255) / 256, 5);
    convW_k<<<cw, 256>>>(Wq, Wk, Wv, Wg, Wo, bW);

    dim3 pg4(EMB / 128, MROWS / 128, 4);   // (4, 32, 4) = 512 CTAs
    proj_all<<<pg4, 256, PJ_SMEM>>>(bA1, bA2, bA3, bX2, bW,
                                    bq, bk, bv, bg, bo,
                                    Qb, Kb, Vb, Gf, out, 0);

    dim3 rg(32, BATCH * HEADS);   // (32, 16) = 512 CTAs, balanced halves
    ret_k<<<rg, 256, RT_SMEM>>>(Qb, Kb, Vb, Pp);

    ret_fin<<<MROWS, 256>>>(Pp, Gf, bX2);

    dim3 pg1(EMB / 128, MROWS / 128, 1);
    proj_all<<<pg1, 256, PJ_SMEM>>>(bA1, bA2, bA3, bX2, bW,
                                    bq, bk, bv, bg, bo,
                                    Qb, Kb, Vb, Gf, out, 1);
}

// round 14
// speedup vs baseline: 1.6948x; 1.4839x over previous
#include <cuda_runtime.h>
#include <cuda_fp16.h>
#include <math.h>
#include <stdint.h>

#define BATCH 2
#define SEQ   2048
#define EMB   512
#define HEADS 8
#define HDIM  64
#define MROWS 4096
#define KW    512    // everything single-term fp16, plain 512-col rows

// ---------------------------------------------------------------------------
// Scratch (device globals; allocation in kernel_launch is forbidden)
// ---------------------------------------------------------------------------
__device__ __align__(16) __half g_bA1[MROWS * KW];
__device__ __align__(16) __half g_bA2[MROWS * KW];
__device__ __align__(16) __half g_bA3[MROWS * KW];
__device__ __align__(16) __half g_bW [5 * EMB * KW];
__device__ __align__(16) __half g_Qb [MROWS * KW];
__device__ __align__(16) __half g_Kb [MROWS * KW];
__device__ __align__(16) __half g_Vb [MROWS * KW];
__device__ __align__(16) float  g_G  [MROWS * EMB];
__device__ __align__(16) __half g_bX2[MROWS * KW];
__device__ __align__(16) float  g_part[2 * MROWS * EMB];
__device__ __align__(16) float g_sin[SEQ * 32];
__device__ __align__(16) float g_cos[SEQ * 32];

// ---------------------------------------------------------------------------
// Helpers
// ---------------------------------------------------------------------------
__device__ __forceinline__ uint32_t smem_u32(const void* p) {
    uint32_t a;
    asm("{ .reg .u64 t; cvta.to.shared.u64 t, %1; cvt.u32.u64 %0, t; }"
        : "=r"(a) : "l"(p));
    return a;
}

__device__ __forceinline__ void mma_f16(float* c, uint32_t a0, uint32_t a1,
                                        uint32_t a2, uint32_t a3,
                                        uint32_t b0, uint32_t b1) {
    asm volatile(
        "mma.sync.aligned.m16n8k16.row.col.f32.f16.f16.f32 "
        "{%0,%1,%2,%3}, {%4,%5,%6,%7}, {%8,%9}, {%0,%1,%2,%3};\n"
        : "+f"(c[0]), "+f"(c[1]), "+f"(c[2]), "+f"(c[3])
        : "r"(a0), "r"(a1), "r"(a2), "r"(a3), "r"(b0), "r"(b1));
}

__device__ __forceinline__ void ldsm4(uint32_t* r, uint32_t addr) {
    asm volatile("ldmatrix.sync.aligned.m8n8.x4.shared.b16 {%0,%1,%2,%3}, [%4];"
                 : "=r"(r[0]), "=r"(r[1]), "=r"(r[2]), "=r"(r[3]) : "r"(addr));
}
__device__ __forceinline__ void ldsm4t(uint32_t* r, uint32_t addr) {
    asm volatile("ldmatrix.sync.aligned.m8n8.x4.trans.shared.b16 {%0,%1,%2,%3}, [%4];"
                 : "=r"(r[0]), "=r"(r[1]), "=r"(r[2]), "=r"(r[3]) : "r"(addr));
}

#define CP16(dst, src) \
    asm volatile("cp.async.cg.shared.global [%0], [%1], 16;" \
                 :: "r"((uint32_t)(dst)), "l"(src))
#define CP_COMMIT() asm volatile("cp.async.commit_group;" ::: "memory")
#define CP_WAIT0()  asm volatile("cp.async.wait_group 0;" ::: "memory")

__device__ __forceinline__ uint32_t pk2h(__half a, __half b) {
    uint16_t lo = *(uint16_t*)&a, hi = *(uint16_t*)&b;
    return (uint32_t)lo | ((uint32_t)hi << 16);
}

// ---------------------------------------------------------------------------
// prep: fp32 -> fp16 conversions (3 activations + 5 weights) + rotary tables
// ---------------------------------------------------------------------------
__device__ __forceinline__ void conv4(const float* __restrict__ src,
                                      __half* __restrict__ dst, int idx) {
    int row = idx >> 7, c = (idx & 127) << 2;
    float4 v = *(const float4*)(src + (size_t)row * EMB + c);
    __half h[4];
    h[0] = __float2half_rn(v.x); h[1] = __float2half_rn(v.y);
    h[2] = __float2half_rn(v.z); h[3] = __float2half_rn(v.w);
    uint2 hp;
    hp.x = pk2h(h[0], h[1]); hp.y = pk2h(h[2], h[3]);
    *(uint2*)(dst + (size_t)row * KW + c) = hp;
}

__global__ void prep_k(const float* __restrict__ q0, const float* __restrict__ k0,
                       const float* __restrict__ v0,
                       const float* __restrict__ w0, const float* __restrict__ w1,
                       const float* __restrict__ w2, const float* __restrict__ w3,
                       const float* __restrict__ w4,
                       __half* __restrict__ a0, __half* __restrict__ a1,
                       __half* __restrict__ a2, __half* __restrict__ wd,
                       float* __restrict__ st, float* __restrict__ ct) {
    const int y = blockIdx.y;
    const int idx = blockIdx.x * blockDim.x + threadIdx.x;
    if (y < 3) {
        if (idx >= MROWS * 128) return;
        const float* s = (y == 0) ? q0 : (y == 1) ? k0 : v0;
        __half* d = (y == 0) ? a0 : (y == 1) ? a1 : a2;
        conv4(s, d, idx);
    } else if (y < 8) {
        if (idx >= EMB * 128) return;
        const float* s;
        switch (y) {
            case 3: s = w0; break;
            case 4: s = w1; break;
            case 5: s = w2; break;
            case 6: s = w3; break;
            default: s = w4; break;
        }
        conv4(s, wd + (size_t)(y - 3) * EMB * KW, idx);
    } else {
        if (idx >= SEQ * 32) return;
        int n = idx >> 5, p = idx & 31;
        float theta = powf(10000.f, -(float)p * (1.0f / 31.0f));
        float sv, cv;
        sincosf((float)n * theta, &sv, &cv);
        st[idx] = sv;
        ct[idx] = cv;
    }
}

// ---------------------------------------------------------------------------
// Projection GEMM (merged, single-term fp16): CTA 128x128, warp 32x64.
// phase 0: z=0 Q(rotary), z=1 K(rotary*.125), z=2 V, z=3 G(silu)
// phase 1: output projection (fp32 out)
// ---------------------------------------------------------------------------
#define PJ_P   144
#define PJ_BUF 18432             // 128 rows * 144 B
#define PJ_SMEM (4 * PJ_BUF)     // 73728
#define PJ_CHUNKS 8

__global__ void __launch_bounds__(256, 2)
proj_all(const __half* __restrict__ bA1, const __half* __restrict__ bA2,
         const __half* __restrict__ bA3, const __half* __restrict__ bX2,
         const __half* __restrict__ bW,
         const float* __restrict__ bq, const float* __restrict__ bk,
         const float* __restrict__ bv, const float* __restrict__ bg,
         const float* __restrict__ bo,
         __half* __restrict__ Qb, __half* __restrict__ Kb,
         __half* __restrict__ Vb, float* __restrict__ Gf,
         float* __restrict__ outp, int phase)
{
    extern __shared__ char sm[];
    const uint32_t smb = smem_u32(sm);
    const int tid = threadIdx.x;
    const int lane = tid & 31, wid = tid >> 5;
    const int g = lane >> 2, tig = lane & 3;
    const int wm = wid >> 1, wn = wid & 1;
    const int mBase = blockIdx.y * 128, nBase = blockIdx.x * 128;
    const int z = blockIdx.z;

    const __half* A;
    const float* bias;
    int mode;
    void* Cout;
    const size_t wOff = (size_t)EMB * KW;
    const __half* W;
    if (phase == 0) {
        if (z == 0)      { A = bA1; W = bW;            bias = bq; mode = 2; Cout = Qb; }
        else if (z == 1) { A = bA2; W = bW + 1 * wOff; bias = bk; mode = 3; Cout = Kb; }
        else if (z == 2) { A = bA3; W = bW + 2 * wOff; bias = bv; mode = 4; Cout = Vb; }
        else             { A = bA1; W = bW + 3 * wOff; bias = bg; mode = 1; Cout = Gf; }
    } else {
        A = bX2; W = bW + 4 * wOff; bias = bo; mode = 0; Cout = outp;
    }

    const int aRow   = lane & 15;
    const int aOff16 = (lane >> 4) * 16;
    const int bRow   = (lane & 7) + ((lane >> 4) << 3);
    const int bOff16 = ((lane >> 3) & 1) * 16;

    float acc[2][8][4];
#pragma unroll
    for (int a = 0; a < 2; a++)
#pragma unroll
        for (int b = 0; b < 8; b++)
#pragma unroll
            for (int c = 0; c < 4; c++) acc[a][b][c] = 0.f;

    const int crow = tid >> 1;
    const int csel = tid & 1;
    const __half* Arow = A + (size_t)(mBase + crow) * KW;
    const __half* Wrow = W + (size_t)(nBase + crow) * KW;

#define LOADC(c) do {                                                          \
    const int _b = (c) & 1;                                                    \
    const uint32_t _ad = smb + _b * PJ_BUF + crow * PJ_P + csel * 64;          \
    const __half* _as = Arow + (c) * 64 + csel * 32;                           \
    _Pragma("unroll")                                                          \
    for (int _i = 0; _i < 4; _i++) CP16(_ad + _i * 16, _as + _i * 8);          \
    const uint32_t _wd = smb + 2 * PJ_BUF + _b * PJ_BUF + crow * PJ_P + csel * 64; \
    const __half* _ws = Wrow + (c) * 64 + csel * 32;                           \
    _Pragma("unroll")                                                          \
    for (int _i = 0; _i < 4; _i++) CP16(_wd + _i * 16, _ws + _i * 8);          \
} while (0)

    LOADC(0);
    CP_COMMIT();

    for (int c = 0; c < PJ_CHUNKS; c++) {
        CP_WAIT0();
        __syncthreads();
        if (c + 1 < PJ_CHUNKS) {
            LOADC(c + 1);
            CP_COMMIT();
        }
        const uint32_t aS = smb + (c & 1) * PJ_BUF;
        const uint32_t wS = smb + 2 * PJ_BUF + (c & 1) * PJ_BUF;
#pragma unroll
        for (int ks = 0; ks < 4; ks++) {
            uint32_t av[2][4];
#pragma unroll
            for (int mt = 0; mt < 2; mt++)
                ldsm4(av[mt], aS + (wm * 32 + mt * 16 + aRow) * PJ_P
                              + ks * 32 + aOff16);
#pragma unroll
            for (int nt2 = 0; nt2 < 4; nt2++) {
                uint32_t bvv[4];
                ldsm4(bvv, wS + (wn * 64 + nt2 * 16 + bRow) * PJ_P
                           + ks * 32 + bOff16);
#pragma unroll
                for (int mt = 0; mt < 2; mt++) {
                    mma_f16(acc[mt][nt2 * 2 + 0],
                            av[mt][0], av[mt][1], av[mt][2], av[mt][3], bvv[0], bvv[1]);
                    mma_f16(acc[mt][nt2 * 2 + 1],
                            av[mt][0], av[mt][1], av[mt][2], av[mt][3], bvv[2], bvv[3]);
                }
            }
        }
    }
#undef LOADC

    // epilogue
#pragma unroll
    for (int mt = 0; mt < 2; mt++) {
#pragma unroll
        for (int half = 0; half < 2; half++) {
            const int row = mBase + wm * 32 + mt * 16 + g + half * 8;
            const int nseq = row & (SEQ - 1);
#pragma unroll
            for (int nt = 0; nt < 8; nt++) {
                const int col = nBase + wn * 64 + nt * 8 + tig * 2;
                float v0 = acc[mt][nt][half * 2 + 0] + __ldg(bias + col);
                float v1 = acc[mt][nt][half * 2 + 1] + __ldg(bias + col + 1);
                if (mode == 0) {
                    *(float2*)((float*)Cout + (size_t)row * EMB + col) =
                        make_float2(v0, v1);
                } else if (mode == 1) {
                    v0 = v0 / (1.f + expf(-v0));
                    v1 = v1 / (1.f + expf(-v1));
                    *(float2*)((float*)Cout + (size_t)row * EMB + col) =
                        make_float2(v0, v1);
                } else {
                    float x = v0, y = v1;
                    if (mode == 2 || mode == 3) {
                        const int d = col & 63, p = d >> 1;
                        const float sv = g_sin[nseq * 32 + p];
                        const float cv = g_cos[nseq * 32 + p];
                        x = v0 * cv - v1 * sv;
                        y = v1 * cv + v0 * sv;
                        if (mode == 3) { x *= 0.125f; y *= 0.125f; }
                    }
                    __half* C = (__half*)Cout;
                    *(uint32_t*)(C + (size_t)row * KW + col) =
                        pk2h(__float2half_rn(x), __float2half_rn(y));
                }
            }
        }
    }
}

// ---------------------------------------------------------------------------
// Retention, single-term fp16 with split-K load balance:
// grid (32, 16): x -> (rb = 15 - (x>>1), shalf = x&1). Partial fp32 sums to
// g_part; ret_fin reduces + GroupNorm + gate + fp16 store.
// ---------------------------------------------------------------------------
#define RT_P   144
#define RT_QS  0
#define RT_KS  18432
#define RT_VS  36864
#define RT_TAB 55296
#define RT_SMEM 56320

__global__ void __launch_bounds__(256, 2)
ret_k(const __half* __restrict__ Qb, const __half* __restrict__ Kb,
      const __half* __restrict__ Vb, float* __restrict__ P)
{
    extern __shared__ char sm[];
    const uint32_t smb = smem_u32(sm);
    float* tab = (float*)(sm + RT_TAB);
    const int tid = threadIdx.x;
    const int lane = tid & 31, wid = tid >> 5;
    const int g = lane >> 2, tig = lane & 3;
    const int rb = 15 - ((int)blockIdx.x >> 1);
    const int shalf = blockIdx.x & 1;
    const int rowBase = rb * 128;
    const int bh = blockIdx.y;
    const int b = bh >> 3, h = bh & 7;

    const int n0 = (rb + 2) >> 1;
    const int s0 = shalf ? n0 : 0;
    const int s1 = shalf ? (rb + 1) : n0;

    const int aRow   = lane & 15;
    const int aOff16 = (lane >> 4) * 16;
    const int bRow   = (lane & 7) + ((lane >> 4) << 3);
    const int bOff16 = ((lane >> 3) & 1) * 16;
    const int vRow   = (lane & 7) + (((lane >> 3) & 1) << 3);
    const int vCol16 = ((lane >> 4) & 1) * 16;
    const uint32_t vAddrBase = smb + RT_VS + vRow * RT_P + vCol16;

    const double la = -3.4657359027997265;   // log(1/32)
    const double lb = -6.2383246250395075;   // log(1/512)
    const float gamma = (float)(1.0 - exp(la + (lb - la) * ((double)h / 7.0)));
    const float lg2g = log2f(gamma);
    if (tid < 256) tab[tid] = exp2f(lg2g * (float)(tid - 128));

    // Q tile: 128 rows x 64 fp16
    if (s0 < s1) {
        const __half* qs = Qb + (size_t)(b * SEQ + rowBase) * KW + h * 64;
        for (int e = tid; e < 128 * 8; e += 256) {
            int r = e >> 3, q = e & 7;
            *(uint4*)(sm + RT_QS + r * RT_P + q * 16) =
                *(const uint4*)(qs + (size_t)r * KW + q * 8);
        }
    }

    float sacc[8][4];
#pragma unroll
    for (int i = 0; i < 8; i++)
#pragma unroll
        for (int j = 0; j < 4; j++) sacc[i][j] = 0.f;

    const uint32_t qAddr = smb + RT_QS + (wid * 16 + aRow) * RT_P + aOff16;

    for (int sT = s0; sT < s1; sT++) {
        const int colBase = sT * 128;
        __syncthreads();
        {
            const __half* ks = Kb + (size_t)(b * SEQ + colBase) * KW + h * 64;
            const __half* vs = Vb + (size_t)(b * SEQ + colBase) * KW + h * 64;
            for (int e = tid; e < 128 * 8; e += 256) {
                int r = e >> 3, q = e & 7;
                *(uint4*)(sm + RT_KS + r * RT_P + q * 16) =
                    *(const uint4*)(ks + (size_t)r * KW + q * 8);
                *(uint4*)(sm + RT_VS + r * RT_P + q * 16) =
                    *(const uint4*)(vs + (size_t)r * KW + q * 8);
            }
        }
        __syncthreads();

        const float basefac = exp2f(lg2g * (float)(rowBase - colBase));
        const bool diag = (sT == rb);
        const int li0 = wid * 16 + g;

#pragma unroll
        for (int qt = 0; qt < 4; qt++) {
            float qk[4][4];
#pragma unroll
            for (int i = 0; i < 4; i++)
#pragma unroll
                for (int j = 0; j < 4; j++) qk[i][j] = 0.f;

#pragma unroll
            for (int ks = 0; ks < 4; ks++) {
                uint32_t aH[4];
                ldsm4(aH, qAddr + ks * 32);
#pragma unroll
                for (int nt2 = 0; nt2 < 2; nt2++) {
                    uint32_t bvv[4];
                    ldsm4(bvv, smb + RT_KS
                          + (qt * 32 + nt2 * 16 + bRow) * RT_P + ks * 32 + bOff16);
                    mma_f16(qk[nt2 * 2 + 0], aH[0], aH[1], aH[2], aH[3], bvv[0], bvv[1]);
                    mma_f16(qk[nt2 * 2 + 1], aH[0], aH[1], aH[2], aH[3], bvv[2], bvv[3]);
                }
            }

            uint32_t sh01[4], sh23[4];
#pragma unroll
            for (int nt = 0; nt < 4; nt++) {
                const int lj = qt * 32 + nt * 8 + tig * 2;
                const int d00 = li0 - lj,     d01 = d00 - 1;
                const int d10 = li0 + 8 - lj, d11 = d10 - 1;
                float w00 = basefac * tab[d00 + 128];
                float w01 = basefac * tab[d01 + 128];
                float w10 = basefac * tab[d10 + 128];
                float w11 = basefac * tab[d11 + 128];
                if (diag && d00 < 0) w00 = 0.f;
                if (diag && d01 < 0) w01 = 0.f;
                if (diag && d10 < 0) w10 = 0.f;
                if (diag && d11 < 0) w11 = 0.f;
                sh01[nt] = pk2h(__float2half_rn(qk[nt][0] * w00),
                                __float2half_rn(qk[nt][1] * w01));
                sh23[nt] = pk2h(__float2half_rn(qk[nt][2] * w10),
                                __float2half_rn(qk[nt][3] * w11));
            }

#pragma unroll
            for (int ksl = 0; ksl < 2; ksl++) {
                uint32_t ah[4] = {sh01[2 * ksl], sh23[2 * ksl],
                                  sh01[2 * ksl + 1], sh23[2 * ksl + 1]};
                const uint32_t vRowAddr = vAddrBase + (qt * 2 + ksl) * 16 * RT_P;
#pragma unroll
                for (int dt = 0; dt < 4; dt++) {
                    uint32_t bhv[4];
                    ldsm4t(bhv, vRowAddr + dt * 32);
                    mma_f16(sacc[dt * 2 + 0], ah[0], ah[1], ah[2], ah[3], bhv[0], bhv[1]);
                    mma_f16(sacc[dt * 2 + 1], ah[0], ah[1], ah[2], ah[3], bhv[2], bhv[3]);
                }
            }
        }
    }

    float* P0 = P + (size_t)shalf * (MROWS * EMB);
    const int mrowA = b * SEQ + rowBase + wid * 16 + g;
    const int mrowB = mrowA + 8;
#pragma unroll
    for (int nt = 0; nt < 8; nt++) {
        const int d = nt * 8 + tig * 2;
        *(float2*)(P0 + (size_t)mrowA * EMB + h * 64 + d) =
            make_float2(sacc[nt][0], sacc[nt][1]);
        *(float2*)(P0 + (size_t)mrowB * EMB + h * 64 + d) =
            make_float2(sacc[nt][2], sacc[nt][3]);
    }
}

// ---------------------------------------------------------------------------
// Reduce partials + GroupNorm + gate + fp16 store. One warp per (row,h).
// ---------------------------------------------------------------------------
__global__ void __launch_bounds__(256)
ret_fin(const float* __restrict__ P, const float* __restrict__ G,
        __half* __restrict__ X2)
{
    const int w = blockIdx.x * 8 + (threadIdx.x >> 5);
    const int lane = threadIdx.x & 31;
    const int mrow = w >> 3, h = w & 7;
    const size_t base = (size_t)mrow * EMB + h * 64 + lane * 2;

    const float2 a = *(const float2*)(P + base);
    const float2 b2 = *(const float2*)(P + (size_t)MROWS * EMB + base);
    const float x0 = a.x + b2.x;
    const float x1 = a.y + b2.y;

    float s1 = x0 + x1;
    float s2 = x0 * x0 + x1 * x1;
#pragma unroll
    for (int m = 16; m >= 1; m >>= 1) {
        s1 += __shfl_xor_sync(0xffffffffu, s1, m);
        s2 += __shfl_xor_sync(0xffffffffu, s2, m);
    }
    const float mean = s1 * (1.f / 64.f);
    float var = fmaxf(s2 * (1.f / 64.f) - mean * mean, 0.f);
    const float inv = rsqrtf(var + 1e-6f);

    const float2 gg = *(const float2*)(G + base);
    const float y0 = (x0 - mean) * inv * gg.x;
    const float y1 = (x1 - mean) * inv * gg.y;

    *(uint32_t*)(X2 + (size_t)mrow * KW + h * 64 + lane * 2) =
        pk2h(__float2half_rn(y0), __float2half_rn(y1));
}

// ---------------------------------------------------------------------------
// Launch
// ---------------------------------------------------------------------------
extern "C" void kernel_launch(void* const* d_in, const int* in_sizes, int n_in,
                              void* d_out, int out_size)
{
    (void)in_sizes; (void)n_in; (void)out_size;
    const float* query = (const float*)d_in[0];
    const float* kin   = (const float*)d_in[1];
    const float* vin   = (const float*)d_in[2];
    const float* Wq = (const float*)d_in[3];  const float* bq = (const float*)d_in[4];
    const float* Wk = (const float*)d_in[5];  const float* bk = (const float*)d_in[6];
    const float* Wv = (const float*)d_in[7];  const float* bv = (const float*)d_in[8];
    const float* Wg = (const float*)d_in[9];  const float* bg = (const float*)d_in[10];
    const float* Wo = (const float*)d_in[11]; const float* bo = (const float*)d_in[12];
    float* out = (float*)d_out;

    float *Gf, *sinp, *cosp, *Pp;
    __half *bA1, *bA2, *bA3, *bW, *Qb, *Kb, *Vb, *bX2;
    cudaGetSymbolAddress((void**)&bA1, g_bA1);
    cudaGetSymbolAddress((void**)&bA2, g_bA2);
    cudaGetSymbolAddress((void**)&bA3, g_bA3);
    cudaGetSymbolAddress((void**)&bW,  g_bW);
    cudaGetSymbolAddress((void**)&Qb,  g_Qb);
    cudaGetSymbolAddress((void**)&Kb,  g_Kb);
    cudaGetSymbolAddress((void**)&Vb,  g_Vb);
    cudaGetSymbolAddress((void**)&Gf,  g_G);
    cudaGetSymbolAddress((void**)&bX2, g_bX2);
    cudaGetSymbolAddress((void**)&Pp,  g_part);
    cudaGetSymbolAddress((void**)&sinp, g_sin);
    cudaGetSymbolAddress((void**)&cosp, g_cos);

    cudaFuncSetAttribute(proj_all, cudaFuncAttributeMaxDynamicSharedMemorySize, PJ_SMEM);
    cudaFuncSetAttribute(ret_k, cudaFuncAttributeMaxDynamicSharedMemorySize, RT_SMEM);

    dim3 pr(2048, 9);
    prep_k<<<pr, 256>>>(query, kin, vin, Wq, Wk, Wv, Wg, Wo,
                        bA1, bA2, bA3, bW, sinp, cosp);

    dim3 pg4(EMB / 128, MROWS / 128, 4);   // (4, 32, 4)
    proj_all<<<pg4, 256, PJ_SMEM>>>(bA1, bA2, bA3, bX2, bW,
                                    bq, bk, bv, bg, bo,
                                    Qb, Kb, Vb, Gf, out, 0);

    dim3 rg(32, BATCH * HEADS);   // (32, 16)
    ret_k<<<rg, 256, RT_SMEM>>>(Qb, Kb, Vb, Pp);

    ret_fin<<<MROWS, 256>>>(Pp, Gf, bX2);

    dim3 pg1(EMB / 128, MROWS / 128, 1);
    proj_all<<<pg1, 256, PJ_SMEM>>>(bA1, bA2, bA3, bX2, bW,
                                    bq, bk, bv, bg, bo,
                                    Qb, Kb, Vb, Gf, out, 1);
}

// round 15
// speedup vs baseline: 1.7536x; 1.0347x over previous
#include <cuda_runtime.h>
#include <cuda_fp16.h>
#include <math.h>
#include <stdint.h>

#define BATCH 2
#define SEQ   2048
#define EMB   512
#define HEADS 8
#define HDIM  64
#define MROWS 4096
#define KW    512    // everything single-term fp16, plain 512-col rows

// ---------------------------------------------------------------------------
// Scratch (device globals; allocation in kernel_launch is forbidden)
// ---------------------------------------------------------------------------
__device__ __align__(16) __half g_bA1[MROWS * KW];
__device__ __align__(16) __half g_bA2[MROWS * KW];
__device__ __align__(16) __half g_bA3[MROWS * KW];
__device__ __align__(16) __half g_bW [5 * EMB * KW];
__device__ __align__(16) __half g_Qb [MROWS * KW];
__device__ __align__(16) __half g_Kb [MROWS * KW];
__device__ __align__(16) __half g_Vb [MROWS * KW];
__device__ __align__(16) float  g_G  [MROWS * EMB];
__device__ __align__(16) __half g_bX2[MROWS * KW];
__device__ __align__(16) float  g_part[2 * MROWS * EMB];
__device__ __align__(16) float g_sin[SEQ * 32];
__device__ __align__(16) float g_cos[SEQ * 32];

// ---------------------------------------------------------------------------
// Helpers
// ---------------------------------------------------------------------------
__device__ __forceinline__ uint32_t smem_u32(const void* p) {
    uint32_t a;
    asm("{ .reg .u64 t; cvta.to.shared.u64 t, %1; cvt.u32.u64 %0, t; }"
        : "=r"(a) : "l"(p));
    return a;
}

__device__ __forceinline__ void mma_f16(float* c, uint32_t a0, uint32_t a1,
                                        uint32_t a2, uint32_t a3,
                                        uint32_t b0, uint32_t b1) {
    asm volatile(
        "mma.sync.aligned.m16n8k16.row.col.f32.f16.f16.f32 "
        "{%0,%1,%2,%3}, {%4,%5,%6,%7}, {%8,%9}, {%0,%1,%2,%3};\n"
        : "+f"(c[0]), "+f"(c[1]), "+f"(c[2]), "+f"(c[3])
        : "r"(a0), "r"(a1), "r"(a2), "r"(a3), "r"(b0), "r"(b1));
}

__device__ __forceinline__ void ldsm4(uint32_t* r, uint32_t addr) {
    asm volatile("ldmatrix.sync.aligned.m8n8.x4.shared.b16 {%0,%1,%2,%3}, [%4];"
                 : "=r"(r[0]), "=r"(r[1]), "=r"(r[2]), "=r"(r[3]) : "r"(addr));
}
__device__ __forceinline__ void ldsm4t(uint32_t* r, uint32_t addr) {
    asm volatile("ldmatrix.sync.aligned.m8n8.x4.trans.shared.b16 {%0,%1,%2,%3}, [%4];"
                 : "=r"(r[0]), "=r"(r[1]), "=r"(r[2]), "=r"(r[3]) : "r"(addr));
}

#define CP16(dst, src) \
    asm volatile("cp.async.cg.shared.global [%0], [%1], 16;" \
                 :: "r"((uint32_t)(dst)), "l"(src))
#define CP_COMMIT() asm volatile("cp.async.commit_group;" ::: "memory")
#define CP_WAIT0()  asm volatile("cp.async.wait_group 0;" ::: "memory")

__device__ __forceinline__ uint32_t pk2h(__half a, __half b) {
    uint16_t lo = *(uint16_t*)&a, hi = *(uint16_t*)&b;
    return (uint32_t)lo | ((uint32_t)hi << 16);
}

// ---------------------------------------------------------------------------
// prep: fp32 -> fp16 conversions (3 activations + 5 weights) + rotary tables.
// Flattened exact grid: 6144 act blocks + 1280 weight blocks + 256 rope.
// ---------------------------------------------------------------------------
__device__ __forceinline__ void conv4(const float* __restrict__ src,
                                      __half* __restrict__ dst, int idx) {
    int row = idx >> 7, c = (idx & 127) << 2;
    float4 v = *(const float4*)(src + (size_t)row * EMB + c);
    __half h[4];
    h[0] = __float2half_rn(v.x); h[1] = __float2half_rn(v.y);
    h[2] = __float2half_rn(v.z); h[3] = __float2half_rn(v.w);
    uint2 hp;
    hp.x = pk2h(h[0], h[1]); hp.y = pk2h(h[2], h[3]);
    *(uint2*)(dst + (size_t)row * KW + c) = hp;
}

__global__ void __launch_bounds__(256)
prep_k(const float* __restrict__ q0, const float* __restrict__ k0,
       const float* __restrict__ v0,
       const float* __restrict__ w0, const float* __restrict__ w1,
       const float* __restrict__ w2, const float* __restrict__ w3,
       const float* __restrict__ w4,
       __half* __restrict__ a0, __half* __restrict__ a1,
       __half* __restrict__ a2, __half* __restrict__ wd,
       float* __restrict__ st, float* __restrict__ ct) {
    const int bid = blockIdx.x;
    const int tid = threadIdx.x;
    if (bid < 6144) {                       // activations: 3 x 2048 blocks
        const int y = bid >> 11;            // /2048
        const int idx = ((bid & 2047) << 8) + tid;
        const float* s = (y == 0) ? q0 : (y == 1) ? k0 : v0;
        __half* d = (y == 0) ? a0 : (y == 1) ? a1 : a2;
        conv4(s, d, idx);
    } else if (bid < 7424) {                // weights: 5 x 256 blocks
        const int r = bid - 6144;
        const int w = r >> 8;               // /256
        const int idx = ((r & 255) << 8) + tid;
        const float* s;
        switch (w) {
            case 0: s = w0; break;
            case 1: s = w1; break;
            case 2: s = w2; break;
            case 3: s = w3; break;
            default: s = w4; break;
        }
        conv4(s, wd + (size_t)w * EMB * KW, idx);
    } else {                                // rope: 256 blocks
        const int idx = ((bid - 7424) << 8) + tid;
        int n = idx >> 5, p = idx & 31;
        float theta = powf(10000.f, -(float)p * (1.0f / 31.0f));
        float sv, cv;
        sincosf((float)n * theta, &sv, &cv);
        st[idx] = sv;
        ct[idx] = cv;
    }
}

// ---------------------------------------------------------------------------
// Projection GEMM (merged, single-term fp16): CTA 128x128, warp 32x64.
// B-fragment loads hoisted per k-step for MLP. Single barrier per chunk.
// phase 0: z=0 Q(rotary), z=1 K(rotary*.125), z=2 V, z=3 G(silu)
// phase 1: output projection (fp32 out)
// ---------------------------------------------------------------------------
#define PJ_P   144
#define PJ_BUF 18432             // 128 rows * 144 B
#define PJ_SMEM (4 * PJ_BUF)     // 73728
#define PJ_CHUNKS 8

__global__ void __launch_bounds__(256, 2)
proj_all(const __half* __restrict__ bA1, const __half* __restrict__ bA2,
         const __half* __restrict__ bA3, const __half* __restrict__ bX2,
         const __half* __restrict__ bW,
         const float* __restrict__ bq, const float* __restrict__ bk,
         const float* __restrict__ bv, const float* __restrict__ bg,
         const float* __restrict__ bo,
         __half* __restrict__ Qb, __half* __restrict__ Kb,
         __half* __restrict__ Vb, float* __restrict__ Gf,
         float* __restrict__ outp, int phase)
{
    extern __shared__ char sm[];
    const uint32_t smb = smem_u32(sm);
    const int tid = threadIdx.x;
    const int lane = tid & 31, wid = tid >> 5;
    const int g = lane >> 2, tig = lane & 3;
    const int wm = wid >> 1, wn = wid & 1;
    const int mBase = blockIdx.y * 128, nBase = blockIdx.x * 128;
    const int z = blockIdx.z;

    const __half* A;
    const float* bias;
    int mode;
    void* Cout;
    const size_t wOff = (size_t)EMB * KW;
    const __half* W;
    if (phase == 0) {
        if (z == 0)      { A = bA1; W = bW;            bias = bq; mode = 2; Cout = Qb; }
        else if (z == 1) { A = bA2; W = bW + 1 * wOff; bias = bk; mode = 3; Cout = Kb; }
        else if (z == 2) { A = bA3; W = bW + 2 * wOff; bias = bv; mode = 4; Cout = Vb; }
        else             { A = bA1; W = bW + 3 * wOff; bias = bg; mode = 1; Cout = Gf; }
    } else {
        A = bX2; W = bW + 4 * wOff; bias = bo; mode = 0; Cout = outp;
    }

    const int aRow   = lane & 15;
    const int aOff16 = (lane >> 4) * 16;
    const int bRow   = (lane & 7) + ((lane >> 4) << 3);
    const int bOff16 = ((lane >> 3) & 1) * 16;

    float acc[2][8][4];
#pragma unroll
    for (int a = 0; a < 2; a++)
#pragma unroll
        for (int b = 0; b < 8; b++)
#pragma unroll
            for (int c = 0; c < 4; c++) acc[a][b][c] = 0.f;

    const int crow = tid >> 1;
    const int csel = tid & 1;
    const __half* Arow = A + (size_t)(mBase + crow) * KW;
    const __half* Wrow = W + (size_t)(nBase + crow) * KW;

#define LOADC(c) do {                                                          \
    const int _b = (c) & 1;                                                    \
    const uint32_t _ad = smb + _b * PJ_BUF + crow * PJ_P + csel * 64;          \
    const __half* _as = Arow + (c) * 64 + csel * 32;                           \
    _Pragma("unroll")                                                          \
    for (int _i = 0; _i < 4; _i++) CP16(_ad + _i * 16, _as + _i * 8);          \
    const uint32_t _wd = smb + 2 * PJ_BUF + _b * PJ_BUF + crow * PJ_P + csel * 64; \
    const __half* _ws = Wrow + (c) * 64 + csel * 32;                           \
    _Pragma("unroll")                                                          \
    for (int _i = 0; _i < 4; _i++) CP16(_wd + _i * 16, _ws + _i * 8);          \
} while (0)

    LOADC(0);
    CP_COMMIT();

    for (int c = 0; c < PJ_CHUNKS; c++) {
        CP_WAIT0();
        __syncthreads();
        if (c + 1 < PJ_CHUNKS) {
            LOADC(c + 1);
            CP_COMMIT();
        }
        const uint32_t aS = smb + (c & 1) * PJ_BUF;
        const uint32_t wS = smb + 2 * PJ_BUF + (c & 1) * PJ_BUF;
#pragma unroll
        for (int ks = 0; ks < 4; ks++) {
            uint32_t av[2][4];
#pragma unroll
            for (int mt = 0; mt < 2; mt++)
                ldsm4(av[mt], aS + (wm * 32 + mt * 16 + aRow) * PJ_P
                              + ks * 32 + aOff16);
            uint32_t bq4[4][4];
#pragma unroll
            for (int nt2 = 0; nt2 < 4; nt2++)
                ldsm4(bq4[nt2], wS + (wn * 64 + nt2 * 16 + bRow) * PJ_P
                                + ks * 32 + bOff16);
#pragma unroll
            for (int nt2 = 0; nt2 < 4; nt2++) {
#pragma unroll
                for (int mt = 0; mt < 2; mt++) {
                    mma_f16(acc[mt][nt2 * 2 + 0],
                            av[mt][0], av[mt][1], av[mt][2], av[mt][3],
                            bq4[nt2][0], bq4[nt2][1]);
                    mma_f16(acc[mt][nt2 * 2 + 1],
                            av[mt][0], av[mt][1], av[mt][2], av[mt][3],
                            bq4[nt2][2], bq4[nt2][3]);
                }
            }
        }
    }
#undef LOADC

    // epilogue
#pragma unroll
    for (int mt = 0; mt < 2; mt++) {
#pragma unroll
        for (int half = 0; half < 2; half++) {
            const int row = mBase + wm * 32 + mt * 16 + g + half * 8;
            const int nseq = row & (SEQ - 1);
#pragma unroll
            for (int nt = 0; nt < 8; nt++) {
                const int col = nBase + wn * 64 + nt * 8 + tig * 2;
                float v0 = acc[mt][nt][half * 2 + 0] + __ldg(bias + col);
                float v1 = acc[mt][nt][half * 2 + 1] + __ldg(bias + col + 1);
                if (mode == 0) {
                    *(float2*)((float*)Cout + (size_t)row * EMB + col) =
                        make_float2(v0, v1);
                } else if (mode == 1) {
                    v0 = v0 / (1.f + expf(-v0));
                    v1 = v1 / (1.f + expf(-v1));
                    *(float2*)((float*)Cout + (size_t)row * EMB + col) =
                        make_float2(v0, v1);
                } else {
                    float x = v0, y = v1;
                    if (mode == 2 || mode == 3) {
                        const int d = col & 63, p = d >> 1;
                        const float sv = g_sin[nseq * 32 + p];
                        const float cv = g_cos[nseq * 32 + p];
                        x = v0 * cv - v1 * sv;
                        y = v1 * cv + v0 * sv;
                        if (mode == 3) { x *= 0.125f; y *= 0.125f; }
                    }
                    __half* C = (__half*)Cout;
                    *(uint32_t*)(C + (size_t)row * KW + col) =
                        pk2h(__float2half_rn(x), __float2half_rn(y));
                }
            }
        }
    }
}

// ---------------------------------------------------------------------------
// Retention, single-term fp16, split-K load balance, double-buffered K/V via
// cp.async (one barrier per s-tile). grid (32, 16): x -> (rb, shalf).
// smem: Q 18KB | K0 18KB | V0 18KB | K1 18KB | V1 18KB | tab -> 93KB, 2 CTA/SM
// ---------------------------------------------------------------------------
#define RT_P    144
#define RT_QS   0
#define RT_KV   18432
#define RT_PAIR 36864            // one (K,V) buffer pair
#define RT_TAB  92160
#define RT_SMEM 93184

__global__ void __launch_bounds__(256, 2)
ret_k(const __half* __restrict__ Qb, const __half* __restrict__ Kb,
      const __half* __restrict__ Vb, float* __restrict__ P)
{
    extern __shared__ char sm[];
    const uint32_t smb = smem_u32(sm);
    float* tab = (float*)(sm + RT_TAB);
    const int tid = threadIdx.x;
    const int lane = tid & 31, wid = tid >> 5;
    const int g = lane >> 2, tig = lane & 3;
    const int rb = 15 - ((int)blockIdx.x >> 1);
    const int shalf = blockIdx.x & 1;
    const int rowBase = rb * 128;
    const int bh = blockIdx.y;
    const int b = bh >> 3, h = bh & 7;

    const int n0 = (rb + 2) >> 1;
    const int s0 = shalf ? n0 : 0;
    const int s1 = shalf ? (rb + 1) : n0;

    const int aRow   = lane & 15;
    const int aOff16 = (lane >> 4) * 16;
    const int bRow   = (lane & 7) + ((lane >> 4) << 3);
    const int bOff16 = ((lane >> 3) & 1) * 16;
    const int vRow   = (lane & 7) + (((lane >> 3) & 1) << 3);
    const int vCol16 = ((lane >> 4) & 1) * 16;

    const double la = -3.4657359027997265;   // log(1/32)
    const double lb = -6.2383246250395075;   // log(1/512)
    const float gamma = (float)(1.0 - exp(la + (lb - la) * ((double)h / 7.0)));
    const float lg2g = log2f(gamma);
    if (tid < 256) tab[tid] = exp2f(lg2g * (float)(tid - 128));

    // cp.async staging addressing: thread -> (row = tid>>1, half = tid&1)
    const int crow = tid >> 1;
    const int csel = tid & 1;
    const __half* Kbase = Kb + (size_t)(b * SEQ) * KW + h * 64
                          + (size_t)crow * KW + csel * 32;
    const __half* Vbase = Vb + (size_t)(b * SEQ) * KW + h * 64
                          + (size_t)crow * KW + csel * 32;
    const uint32_t stDst = smb + RT_KV + crow * RT_P + csel * 64;

#define LOADKV(sT, buf) do {                                                  \
    const size_t _go = (size_t)(sT) * 128 * KW;                               \
    const uint32_t _kd = stDst + (uint32_t)(buf) * RT_PAIR;                   \
    const __half* _ks = Kbase + _go;                                          \
    const __half* _vs = Vbase + _go;                                          \
    _Pragma("unroll")                                                         \
    for (int _i = 0; _i < 4; _i++) CP16(_kd + _i * 16, _ks + _i * 8);         \
    _Pragma("unroll")                                                         \
    for (int _i = 0; _i < 4; _i++) CP16(_kd + 18432 + _i * 16, _vs + _i * 8); \
} while (0)

    // Q tile: 128 rows x 64 fp16
    if (s0 < s1) {
        const __half* qs = Qb + (size_t)(b * SEQ + rowBase) * KW + h * 64;
        for (int e = tid; e < 128 * 8; e += 256) {
            int r = e >> 3, q = e & 7;
            *(uint4*)(sm + RT_QS + r * RT_P + q * 16) =
                *(const uint4*)(qs + (size_t)r * KW + q * 8);
        }
        LOADKV(s0, 0);
        CP_COMMIT();
    }

    float sacc[8][4];
#pragma unroll
    for (int i = 0; i < 8; i++)
#pragma unroll
        for (int j = 0; j < 4; j++) sacc[i][j] = 0.f;

    const uint32_t qAddr = smb + RT_QS + (wid * 16 + aRow) * RT_P + aOff16;

    for (int sT = s0; sT < s1; sT++) {
        CP_WAIT0();
        __syncthreads();
        if (sT + 1 < s1) {
            LOADKV(sT + 1, (sT + 1 - s0) & 1);
            CP_COMMIT();
        }
        const uint32_t kvB = smb + RT_KV + (uint32_t)((sT - s0) & 1) * RT_PAIR;
        const uint32_t vAddrBase = kvB + 18432 + vRow * RT_P + vCol16;

        const int colBase = sT * 128;
        const float basefac = exp2f(lg2g * (float)(rowBase - colBase));
        const bool diag = (sT == rb);
        const int li0 = wid * 16 + g;

#pragma unroll
        for (int qt = 0; qt < 4; qt++) {
            float qk[4][4];
#pragma unroll
            for (int i = 0; i < 4; i++)
#pragma unroll
                for (int j = 0; j < 4; j++) qk[i][j] = 0.f;

#pragma unroll
            for (int ks = 0; ks < 4; ks++) {
                uint32_t aH[4];
                ldsm4(aH, qAddr + ks * 32);
#pragma unroll
                for (int nt2 = 0; nt2 < 2; nt2++) {
                    uint32_t bvv[4];
                    ldsm4(bvv, kvB + (qt * 32 + nt2 * 16 + bRow) * RT_P
                               + ks * 32 + bOff16);
                    mma_f16(qk[nt2 * 2 + 0], aH[0], aH[1], aH[2], aH[3], bvv[0], bvv[1]);
                    mma_f16(qk[nt2 * 2 + 1], aH[0], aH[1], aH[2], aH[3], bvv[2], bvv[3]);
                }
            }

            uint32_t sh01[4], sh23[4];
#pragma unroll
            for (int nt = 0; nt < 4; nt++) {
                const int lj = qt * 32 + nt * 8 + tig * 2;
                const int d00 = li0 - lj,     d01 = d00 - 1;
                const int d10 = li0 + 8 - lj, d11 = d10 - 1;
                float w00 = basefac * tab[d00 + 128];
                float w01 = basefac * tab[d01 + 128];
                float w10 = basefac * tab[d10 + 128];
                float w11 = basefac * tab[d11 + 128];
                if (diag && d00 < 0) w00 = 0.f;
                if (diag && d01 < 0) w01 = 0.f;
                if (diag && d10 < 0) w10 = 0.f;
                if (diag && d11 < 0) w11 = 0.f;
                sh01[nt] = pk2h(__float2half_rn(qk[nt][0] * w00),
                                __float2half_rn(qk[nt][1] * w01));
                sh23[nt] = pk2h(__float2half_rn(qk[nt][2] * w10),
                                __float2half_rn(qk[nt][3] * w11));
            }

#pragma unroll
            for (int ksl = 0; ksl < 2; ksl++) {
                uint32_t ah[4] = {sh01[2 * ksl], sh23[2 * ksl],
                                  sh01[2 * ksl + 1], sh23[2 * ksl + 1]};
                const uint32_t vRowAddr = vAddrBase + (qt * 2 + ksl) * 16 * RT_P;
#pragma unroll
                for (int dt = 0; dt < 4; dt++) {
                    uint32_t bhv[4];
                    ldsm4t(bhv, vRowAddr + dt * 32);
                    mma_f16(sacc[dt * 2 + 0], ah[0], ah[1], ah[2], ah[3], bhv[0], bhv[1]);
                    mma_f16(sacc[dt * 2 + 1], ah[0], ah[1], ah[2], ah[3], bhv[2], bhv[3]);
                }
            }
        }
    }
#undef LOADKV

    float* P0 = P + (size_t)shalf * (MROWS * EMB);
    const int mrowA = b * SEQ + rowBase + wid * 16 + g;
    const int mrowB = mrowA + 8;
#pragma unroll
    for (int nt = 0; nt < 8; nt++) {
        const int d = nt * 8 + tig * 2;
        *(float2*)(P0 + (size_t)mrowA * EMB + h * 64 + d) =
            make_float2(sacc[nt][0], sacc[nt][1]);
        *(float2*)(P0 + (size_t)mrowB * EMB + h * 64 + d) =
            make_float2(sacc[nt][2], sacc[nt][3]);
    }
}

// ---------------------------------------------------------------------------
// Reduce partials + GroupNorm + gate + fp16 store. One warp per (row,h).
// ---------------------------------------------------------------------------
__global__ void __launch_bounds__(256)
ret_fin(const float* __restrict__ P, const float* __restrict__ G,
        __half* __restrict__ X2)
{
    const int w = blockIdx.x * 8 + (threadIdx.x >> 5);
    const int lane = threadIdx.x & 31;
    const int mrow = w >> 3, h = w & 7;
    const size_t base = (size_t)mrow * EMB + h * 64 + lane * 2;

    const float2 a = *(const float2*)(P + base);
    const float2 b2 = *(const float2*)(P + (size_t)MROWS * EMB + base);
    const float x0 = a.x + b2.x;
    const float x1 = a.y + b2.y;

    float s1 = x0 + x1;
    float s2 = x0 * x0 + x1 * x1;
#pragma unroll
    for (int m = 16; m >= 1; m >>= 1) {
        s1 += __shfl_xor_sync(0xffffffffu, s1, m);
        s2 += __shfl_xor_sync(0xffffffffu, s2, m);
    }
    const float mean = s1 * (1.f / 64.f);
    float var = fmaxf(s2 * (1.f / 64.f) - mean * mean, 0.f);
    const float inv = rsqrtf(var + 1e-6f);

    const float2 gg = *(const float2*)(G + base);
    const float y0 = (x0 - mean) * inv * gg.x;
    const float y1 = (x1 - mean) * inv * gg.y;

    *(uint32_t*)(X2 + (size_t)mrow * KW + h * 64 + lane * 2) =
        pk2h(__float2half_rn(y0), __float2half_rn(y1));
}

// ---------------------------------------------------------------------------
// Launch
// ---------------------------------------------------------------------------
extern "C" void kernel_launch(void* const* d_in, const int* in_sizes, int n_in,
                              void* d_out, int out_size)
{
    (void)in_sizes; (void)n_in; (void)out_size;
    const float* query = (const float*)d_in[0];
    const float* kin   = (const float*)d_in[1];
    const float* vin   = (const float*)d_in[2];
    const float* Wq = (const float*)d_in[3];  const float* bq = (const float*)d_in[4];
    const float* Wk = (const float*)d_in[5];  const float* bk = (const float*)d_in[6];
    const float* Wv = (const float*)d_in[7];  const float* bv = (const float*)d_in[8];
    const float* Wg = (const float*)d_in[9];  const float* bg = (const float*)d_in[10];
    const float* Wo = (const float*)d_in[11]; const float* bo = (const float*)d_in[12];
    float* out = (float*)d_out;

    float *Gf, *sinp, *cosp, *Pp;
    __half *bA1, *bA2, *bA3, *bW, *Qb, *Kb, *Vb, *bX2;
    cudaGetSymbolAddress((void**)&bA1, g_bA1);
    cudaGetSymbolAddress((void**)&bA2, g_bA2);
    cudaGetSymbolAddress((void**)&bA3, g_bA3);
    cudaGetSymbolAddress((void**)&bW,  g_bW);
    cudaGetSymbolAddress((void**)&Qb,  g_Qb);
    cudaGetSymbolAddress((void**)&Kb,  g_Kb);
    cudaGetSymbolAddress((void**)&Vb,  g_Vb);
    cudaGetSymbolAddress((void**)&Gf,  g_G);
    cudaGetSymbolAddress((void**)&bX2, g_bX2);
    cudaGetSymbolAddress((void**)&Pp,  g_part);
    cudaGetSymbolAddress((void**)&sinp, g_sin);
    cudaGetSymbolAddress((void**)&cosp, g_cos);

    cudaFuncSetAttribute(proj_all, cudaFuncAttributeMaxDynamicSharedMemorySize, PJ_SMEM);
    cudaFuncSetAttribute(ret_k, cudaFuncAttributeMaxDynamicSharedMemorySize, RT_SMEM);

    prep_k<<<7680, 256>>>(query, kin, vin, Wq, Wk, Wv, Wg, Wo,
                          bA1, bA2, bA3, bW, sinp, cosp);

    dim3 pg4(EMB / 128, MROWS / 128, 4);   // (4, 32, 4)
    proj_all<<<pg4, 256, PJ_SMEM>>>(bA1, bA2, bA3, bX2, bW,
                                    bq, bk, bv, bg, bo,
                                    Qb, Kb, Vb, Gf, out, 0);

    dim3 rg(32, BATCH * HEADS);   // (32, 16)
    ret_k<<<rg, 256, RT_SMEM>>>(Qb, Kb, Vb, Pp);

    ret_fin<<<MROWS, 256>>>(Pp, Gf, bX2);

    dim3 pg1(EMB / 128, MROWS / 128, 1);
    proj_all<<<pg1, 256, PJ_SMEM>>>(bA1, bA2, bA3, bX2, bW,
                                    bq, bk, bv, bg, bo,
                                    Qb, Kb, Vb, Gf, out, 1);
}